// round 12
// baseline (speedup 1.0000x reference)
#include <cuda_runtime.h>
#include <cuda_bf16.h>
#include <math.h>
#include <stdint.h>

#define NB    32
#define CH    512
#define WD    28
#define HDIM  28
#define NPIX  784
#define HEADS 8
#define DH    64

#if defined(__CUDA_ARCH__) && (defined(__CUDA_ARCH_FEAT_SM103_ALL) || defined(__CUDA_ARCH_FEAT_SM100_ALL))
#define HAS_TC 1
#else
#define HAS_TC 0
#endif

// ---------------- global scratch (bf16 hi/lo split) ----------------
__device__ __align__(16) __nv_bfloat16 g_xh[NB*NPIX*CH];   // x^T [b][n][c]
__device__ __align__(16) __nv_bfloat16 g_xl[NB*NPIX*CH];
__device__ __align__(16) __nv_bfloat16 g_qh[NB*NPIX*CH];   // q^T [b][n][o]
__device__ __align__(16) __nv_bfloat16 g_ql[NB*NPIX*CH];
__device__ __align__(16) __nv_bfloat16 g_kh[NB*NPIX*CH];
__device__ __align__(16) __nv_bfloat16 g_kl[NB*NPIX*CH];
__device__ __align__(16) __nv_bfloat16 g_voh[NB*CH*NPIX];  // v [b][o][n]
__device__ __align__(16) __nv_bfloat16 g_vol[NB*CH*NPIX];
__device__ __align__(16) __nv_bfloat16 g_ph[HEADS*NPIX*DH]; // pos^T [h][n][d]
__device__ __align__(16) __nv_bfloat16 g_pl[HEADS*NPIX*DH];
__device__ __align__(16) __nv_bfloat16 g_wqh[CH*CH];       // W [o][c]
__device__ __align__(16) __nv_bfloat16 g_wql[CH*CH];
__device__ __align__(16) __nv_bfloat16 g_wkh[CH*CH];
__device__ __align__(16) __nv_bfloat16 g_wkl[CH*CH];
__device__ __align__(16) __nv_bfloat16 g_wvh[CH*CH];
__device__ __align__(16) __nv_bfloat16 g_wvl[CH*CH];

// ---------------- helpers ----------------
__device__ __forceinline__ uint32_t smem_u32(const void* p) {
    uint32_t a;
    asm("{ .reg .u64 t; cvta.to.shared.u64 t, %1; cvt.u32.u64 %0, t; }"
        : "=r"(a) : "l"(p));
    return a;
}
__device__ __forceinline__ void split2(float a, float b, uint32_t& hi, uint32_t& lo) {
    __nv_bfloat16 ah = __float2bfloat16(a);
    __nv_bfloat16 bh = __float2bfloat16(b);
    __nv_bfloat16 al = __float2bfloat16(a - __bfloat162float(ah));
    __nv_bfloat16 bl = __float2bfloat16(b - __bfloat162float(bh));
    __nv_bfloat162 h2; h2.x = ah; h2.y = bh;
    __nv_bfloat162 l2; l2.x = al; l2.y = bl;
    hi = *(uint32_t*)&h2; lo = *(uint32_t*)&l2;
}
__device__ __forceinline__ void split1(float a, __nv_bfloat16& hi, __nv_bfloat16& lo) {
    hi = __float2bfloat16(a);
    lo = __float2bfloat16(a - __bfloat162float(hi));
}

#if HAS_TC
__device__ __forceinline__ uint32_t elect1() {
    uint32_t p;
    asm volatile("{\n\t.reg .pred p;\n\telect.sync _|p, 0xFFFFFFFF;\n\t"
                 "selp.b32 %0, 1, 0, p;\n\t}" : "=r"(p));
    return p;
}
#define TC_ALLOC(sa, n)   asm volatile("tcgen05.alloc.cta_group::1.sync.aligned.shared::cta.b32 [%0], %1;" :: "r"(sa), "r"(n) : "memory")
#define TC_RELINQ()       asm volatile("tcgen05.relinquish_alloc_permit.cta_group::1.sync.aligned;")
#define TC_DEALLOC(t, n)  asm volatile("tcgen05.dealloc.cta_group::1.sync.aligned.b32 %0, %1;" :: "r"(t), "r"(n))
#define TC_COMMIT(mb)     asm volatile("tcgen05.commit.cta_group::1.mbarrier::arrive::one.shared::cluster.b64 [%0];" :: "r"(mb) : "memory")
#define TC_WAIT_LD()      asm volatile("tcgen05.wait::ld.sync.aligned;" ::: "memory")
#define TC_WAIT_ST()      asm volatile("tcgen05.wait::st.sync.aligned;" ::: "memory")
#define TC_FENCE_AFTER()  asm volatile("tcgen05.fence::after_thread_sync;" ::: "memory")
#define TC_FENCE_BEFORE() asm volatile("tcgen05.fence::before_thread_sync;" ::: "memory")
#define FENCE_ASYNC()     asm volatile("fence.proxy.async.shared::cta;" ::: "memory")
#define MBAR_INIT(mb, c)  asm volatile("mbarrier.init.shared.b64 [%0], %1;" :: "r"(mb), "r"(c) : "memory")

#define MBAR_WAIT(mb, par) do {                                              \
    uint32_t _mb = (mb); uint32_t _p = (par); uint32_t _done;                \
    asm volatile("{\n\t.reg .pred p;\n\t"                                    \
        "mbarrier.try_wait.parity.acquire.cta.shared::cta.b64 p, [%1], %2;\n\t" \
        "selp.b32 %0, 1, 0, p;\n\t}"                                         \
        : "=r"(_done) : "r"(_mb), "r"(_p) : "memory");                       \
    if (!_done) {                                                            \
        asm volatile("{\n\t.reg .pred P1;\n\t"                               \
            "WL_%=:\n\t"                                                     \
            "mbarrier.try_wait.parity.acquire.cta.shared::cta.b64 P1, [%0], %1, 0x989680;\n\t" \
            "@P1 bra.uni WD_%=;\n\tbra.uni WL_%=;\n\tWD_%=:\n\t}"            \
            :: "r"(_mb), "r"(_p) : "memory");                                \
    }                                                                        \
} while (0)

#define LDTM_X32(r, addr)                                                    \
    asm volatile("tcgen05.ld.sync.aligned.32x32b.x32.b32 "                   \
        "{%0,%1,%2,%3,%4,%5,%6,%7,%8,%9,%10,%11,%12,%13,%14,%15,"            \
        "%16,%17,%18,%19,%20,%21,%22,%23,%24,%25,%26,%27,%28,%29,%30,%31}, [%32];" \
        : "=r"((r)[0]),"=r"((r)[1]),"=r"((r)[2]),"=r"((r)[3]),               \
          "=r"((r)[4]),"=r"((r)[5]),"=r"((r)[6]),"=r"((r)[7]),               \
          "=r"((r)[8]),"=r"((r)[9]),"=r"((r)[10]),"=r"((r)[11]),             \
          "=r"((r)[12]),"=r"((r)[13]),"=r"((r)[14]),"=r"((r)[15]),           \
          "=r"((r)[16]),"=r"((r)[17]),"=r"((r)[18]),"=r"((r)[19]),           \
          "=r"((r)[20]),"=r"((r)[21]),"=r"((r)[22]),"=r"((r)[23]),           \
          "=r"((r)[24]),"=r"((r)[25]),"=r"((r)[26]),"=r"((r)[27]),           \
          "=r"((r)[28]),"=r"((r)[29]),"=r"((r)[30]),"=r"((r)[31])            \
        : "r"(addr))

#define STTM_X32(addr, r)                                                    \
    asm volatile("tcgen05.st.sync.aligned.32x32b.x32.b32 [%0], "             \
        "{%1,%2,%3,%4,%5,%6,%7,%8,%9,%10,%11,%12,%13,%14,%15,%16,"           \
        "%17,%18,%19,%20,%21,%22,%23,%24,%25,%26,%27,%28,%29,%30,%31,%32};"  \
        :: "r"(addr),                                                        \
           "r"((r)[0]),"r"((r)[1]),"r"((r)[2]),"r"((r)[3]),                  \
           "r"((r)[4]),"r"((r)[5]),"r"((r)[6]),"r"((r)[7]),                  \
           "r"((r)[8]),"r"((r)[9]),"r"((r)[10]),"r"((r)[11]),                \
           "r"((r)[12]),"r"((r)[13]),"r"((r)[14]),"r"((r)[15]),              \
           "r"((r)[16]),"r"((r)[17]),"r"((r)[18]),"r"((r)[19]),              \
           "r"((r)[20]),"r"((r)[21]),"r"((r)[22]),"r"((r)[23]),              \
           "r"((r)[24]),"r"((r)[25]),"r"((r)[26]),"r"((r)[27]),              \
           "r"((r)[28]),"r"((r)[29]),"r"((r)[30]),"r"((r)[31])               \
        : "memory")

__device__ __forceinline__ void mma_f16_ts(uint32_t d, uint32_t a_tmem, uint64_t b,
                                           uint32_t idesc, bool acc) {
    uint32_t en = acc ? 1u : 0u;
    asm volatile("{\n\t.reg .pred p;\n\tsetp.ne.u32 p, %5, 0;\n\t"
        "tcgen05.mma.cta_group::1.kind::f16 [%0], [%1], %2, %3, {%4,%4,%4,%4}, p;\n\t}"
        :: "r"(d), "r"(a_tmem), "l"(b), "r"(idesc), "r"(0u), "r"(en) : "memory");
}
__device__ __forceinline__ uint64_t mkdesc_k(uint32_t addr) {   // SW128, LBO=1, SBO=64
    return ((2ull<<61)|(1ull<<46)|(64ull<<32)|(1ull<<16)) | ((uint64_t)(addr>>4)&0x3FFF);
}
#define IDESC_128 ((1u<<4)|(1u<<7)|(1u<<10)|((128/8)<<17)|((128/16)<<24))
#define IDESC_64  ((1u<<4)|(1u<<7)|(1u<<10)|((64/8)<<17)|((128/16)<<24))

__device__ __forceinline__ uint32_t sw_off(int row, int byte_in_row) {
    uint32_t off = (uint32_t)(row*128 + byte_in_row);
    return off ^ ((off >> 3) & 0x70);
}
#endif  // HAS_TC

// ---------------------------------------------------------------------------
// Prep kernels
// ---------------------------------------------------------------------------
__global__ void pos_kernel(const float* __restrict__ rel_h,
                           const float* __restrict__ rel_w) {
    int idx = blockIdx.x * 256 + threadIdx.x;
    if (idx >= HEADS*DH*NPIX) return;
    int n  = idx % NPIX;
    int hd = idx / NPIX;
    int h = hd >> 6, d = hd & 63;
    float v = rel_h[hd*HDIM + (n % HDIM)] + rel_w[hd*WD + (n / HDIM)];
    __nv_bfloat16 hi, lo;
    split1(v, hi, lo);
    size_t t = ((size_t)h*NPIX + n)*DH + d;
    g_ph[t] = hi; g_pl[t] = lo;
}

__global__ void split_x_kernel(const float* __restrict__ x) {
    __shared__ float t[32][33];
    const int bb = blockIdx.z;
    const int c0 = blockIdx.y * 32;
    const int n0 = blockIdx.x * 32;
    const int tx = threadIdx.x, ty = threadIdx.y;   // 32 x 8
    #pragma unroll
    for (int i = 0; i < 4; i++) {
        int c = c0 + ty + i*8;
        int n = n0 + tx;
        t[ty + i*8][tx] = (n < NPIX) ? x[((size_t)bb*CH + c)*NPIX + n] : 0.f;
    }
    __syncthreads();
    #pragma unroll
    for (int i = 0; i < 4; i++) {
        int n = n0 + ty + i*8;
        if (n < NPIX) {
            float v = t[tx][ty + i*8];
            __nv_bfloat16 hi, lo;
            split1(v, hi, lo);
            size_t d = ((size_t)bb*NPIX + n)*CH + c0 + tx;
            g_xh[d] = hi; g_xl[d] = lo;
        }
    }
}

__global__ void split_w_kernel(const float* __restrict__ wq,
                               const float* __restrict__ wk,
                               const float* __restrict__ wv) {
    int idx = blockIdx.x * 256 + threadIdx.x;
    if (idx >= 3*CH*CH) return;
    int m = idx / (CH*CH);
    int e = idx % (CH*CH);
    const float* src = (m == 0) ? wq : (m == 1) ? wk : wv;
    __nv_bfloat16* dh = (m == 0) ? g_wqh : (m == 1) ? g_wkh : g_wvh;
    __nv_bfloat16* dl = (m == 0) ? g_wql : (m == 1) ? g_wkl : g_wvl;
    __nv_bfloat16 hi, lo;
    split1(src[e], hi, lo);
    dh[e] = hi; dl[e] = lo;
}

// ---------------------------------------------------------------------------
// Merged QKV projection, N=64 o-tiles, 256 TMEM cols, 2 CTAs/SM.
// Block = 128 n-rows x 64 o-cols x {q,k,v}.
// TMEM: A (hi 0-31, lo 32-63) single-buffer | Dq 64-127 | Dk 128-191 | Dv 192-255.
// smem: ctrl+bias [0,2048) | 2 x 48KB B chunk buffers (6 regions x 8KB).
// Commit ck -> mbar[ck&1], parity (ck>>1)&1.
// ---------------------------------------------------------------------------
#define PB_OFF  2048
#define PCHUNK  49152                       /* 6 x 8KB */
#define PROJ_SMEM (PB_OFF + 2*PCHUNK)       /* 100352 B */
#define VT_STRIDE 136

__global__ __launch_bounds__(256, 2)
void qkv_tc_kernel(const float* __restrict__ bq,
                   const float* __restrict__ bk,
                   const float* __restrict__ bv) {
#if HAS_TC
    extern __shared__ char smem[];
    const uint32_t sb = smem_u32(smem);
    const int tid = threadIdx.x;
    const int wid = tid >> 5, lid = tid & 31;
    const int chh = wid >> 2;                 // 0 = hi plane, 1 = lo plane
    const int irow = (wid & 3)*32 + lid;      // n-row within tile
    const uint32_t woff = (uint32_t)(wid & 3) << 21;
    const int bb = blockIdx.z;
    const int n0 = blockIdx.x * 128;
    const int o0 = blockIdx.y * 64;

    if (wid == 0) { TC_ALLOC(sb + 0, 256); TC_RELINQ(); }
    if (tid == 0) { MBAR_INIT(sb + 8, 1); MBAR_INIT(sb + 16, 1); }
    float* bias_s = (float*)(smem + 64);      // [3][64]
    if (tid < 64) {
        bias_s[tid]       = bq[o0 + tid];
        bias_s[64 + tid]  = bk[o0 + tid];
        bias_s[128 + tid] = bv[o0 + tid];
    }
    __syncthreads();
    uint32_t tmem;
    asm volatile("ld.shared.b32 %0, [%1];" : "=r"(tmem) : "r"(sb + 0));

    const size_t xb = (size_t)bb*NPIX*CH;
    const int a_row = n0 + irow;
    const bool a_ok = (a_row < NPIX);
    const __nv_bfloat16* Asrc = (chh ? g_xl : g_xh) + xb;

    // B chunk loader: 6 regions (wq,wq,wk,wk,wv,wv × hi/lo) x [64 o-rows][64 K]
    #define LOADB(ck) do {                                                   \
        int _c0 = (ck)*64, _buf = (ck)&1;                                    \
        _Pragma("unroll")                                                    \
        for (int it = 0; it < 12; it++) {                                    \
            int lin = tid + it*256;                                          \
            int reg = lin >> 9;                                              \
            int r   = (lin >> 3) & 63;                                       \
            int u   = lin & 7;                                               \
            const __nv_bfloat16* _src =                                      \
                (reg == 0) ? g_wqh : (reg == 1) ? g_wql :                    \
                (reg == 2) ? g_wkh : (reg == 3) ? g_wkl :                    \
                (reg == 4) ? g_wvh : g_wvl;                                  \
            uint4 v = *(const uint4*)(_src + (size_t)(o0 + r)*CH + _c0 + u*8); \
            *(uint4*)(smem + PB_OFF + _buf*PCHUNK + reg*8192 + sw_off(r, u*16)) = v; \
        }                                                                    \
    } while (0)

    LOADB(0);
    FENCE_ASYNC();

    for (int ck = 0; ck < 8; ck++) {
        int buf = ck & 1;
        // A regs load (no hazard; overlaps the wait below)
        uint32_t ar[32];
        {
            const uint32_t* as = (const uint32_t*)(Asrc + (size_t)a_row*CH + ck*64);
            #pragma unroll
            for (int c = 0; c < 32; c++) ar[c] = a_ok ? as[c] : 0u;
        }
        if (ck >= 1)   // MMA(ck-1) done: frees A cols + B buf (ck+1)&1
            MBAR_WAIT(sb + 8 + (uint32_t)((ck - 1) & 1)*8, (uint32_t)(((ck - 1) >> 1) & 1));
        STTM_X32(tmem + chh*32 + woff, ar);
        TC_WAIT_ST();
        TC_FENCE_BEFORE();
        __syncthreads();   // STTM(all) + LOADB(ck) stores visible

        if (wid == 0) {
            TC_FENCE_AFTER();
            if (elect1()) {
                #pragma unroll
                for (int t = 0; t < 3; t++) {
                    uint32_t base = sb + PB_OFF + buf*PCHUNK + (2*t)*8192;
                    uint64_t dh = mkdesc_k(base);
                    uint64_t dl = mkdesc_k(base + 8192);
                    uint32_t D = tmem + 64 + t*64;
                    #pragma unroll
                    for (int s = 0; s < 4; s++) {
                        uint32_t aH = tmem + s*8;
                        uint32_t aL = tmem + 32 + s*8;
                        mma_f16_ts(D, aH, dh + s*2, IDESC_64, !(ck == 0 && s == 0));
                        mma_f16_ts(D, aH, dl + s*2, IDESC_64, true);
                        mma_f16_ts(D, aL, dh + s*2, IDESC_64, true);
                    }
                }
                TC_COMMIT(sb + 8 + (uint32_t)(ck & 1)*8);
            }
        }
        if (ck < 7) LOADB(ck + 1);
        FENCE_ASYNC();
    }
    MBAR_WAIT(sb + 8 + 8, 1u);   // commit 7: mbar[1], parity 1
    #undef LOADB
    TC_FENCE_AFTER();

    // ---- epilogue ----
    __nv_bfloat16* vsm_h = (__nv_bfloat16*)(smem + PB_OFF);
    __nv_bfloat16* vsm_l = (__nv_bfloat16*)(smem + PB_OFF + 20480);

    #pragma unroll
    for (int t = 0; t < 3; t++) {
        float sv[32];
        {
            uint32_t rr[32];
            LDTM_X32(rr, tmem + 64 + t*64 + chh*32);
            TC_WAIT_LD();
            #pragma unroll
            for (int c = 0; c < 32; c++)
                sv[c] = __uint_as_float(rr[c]) + bias_s[t*64 + chh*32 + c];
        }

        if (t < 2) {
            if (a_ok) {
                uint32_t hw[16], lw[16];
                #pragma unroll
                for (int c = 0; c < 16; c++) split2(sv[2*c], sv[2*c+1], hw[c], lw[c]);
                __nv_bfloat16* OH = (t == 0) ? g_qh : g_kh;
                __nv_bfloat16* OL = (t == 0) ? g_ql : g_kl;
                size_t d = xb + (size_t)a_row*CH + o0 + chh*32;
                #pragma unroll
                for (int u = 0; u < 2; u++) {
                    *(uint4*)&OH[d + u*16]     = *(uint4*)&hw[u*8];
                    *(uint4*)&OH[d + u*16 + 8] = *(uint4*)&hw[u*8 + 4];
                    *(uint4*)&OL[d + u*16]     = *(uint4*)&lw[u*8];
                    *(uint4*)&OL[d + u*16 + 8] = *(uint4*)&lw[u*8 + 4];
                }
            }
        } else {
            // v: transpose via smem (thread owns row n=irow, cols o=chh*32+c)
            __syncthreads();
            #pragma unroll
            for (int c = 0; c < 32; c++) {
                __nv_bfloat16 hi, lo;
                split1(sv[c], hi, lo);
                vsm_h[(chh*32 + c)*VT_STRIDE + irow] = hi;
                vsm_l[(chh*32 + c)*VT_STRIDE + irow] = lo;
            }
            __syncthreads();
            // coalesced store: thread -> (o = tid>>2, quarter = tid&3)
            int o = tid >> 2, qd = tid & 3;
            size_t gdst = ((size_t)bb*CH + o0 + o)*NPIX + n0;
            #pragma unroll
            for (int u = 0; u < 4; u++) {
                int n = qd*32 + u*8;
                if (n0 + n < NPIX) {
                    *(uint4*)&g_voh[gdst + n] = *(const uint4*)&vsm_h[o*VT_STRIDE + n];
                    *(uint4*)&g_vol[gdst + n] = *(const uint4*)&vsm_l[o*VT_STRIDE + n];
                }
            }
        }
    }
    __syncthreads();
    if (wid == 0) TC_DEALLOC(tmem, 256);
#else
    (void)bq; (void)bk; (void)bv;
#endif
}

// ---------------------------------------------------------------------------
// Pipelined tensor-core flash attention — single merged commit per iteration.
// smem: ctrl [0,64) | red [64,2112) | K bufs 2x64KB @4096 | V bufs 2x32KB.
// TMEM: QH 0 | QL 64 | PH 128 | PL 192 | S 256 | O 384.
// One mbar (sb+8): commits C0 = S(0); C_{jt+1} = [PV(jt), S(jt+1)].
// ---------------------------------------------------------------------------
#define AT_KB(b) (4096 + (b)*65536)
#define AT_VB(b) (4096 + 131072 + (b)*32768)
#define TC_SMEM  (4096 + 131072 + 65536)    /* 200704 B */
#define TMC_QH 0
#define TMC_QL 64
#define TMC_PH 128
#define TMC_PL 192
#define TMC_S  256
#define TMC_O  384

__global__ __launch_bounds__(256, 1)
void attn_tc_kernel(float* __restrict__ out) {
#if HAS_TC
    extern __shared__ char smem[];
    const uint32_t sb = smem_u32(smem);
    const int tid = threadIdx.x;
    const int wid = tid >> 5, lid = tid & 31;
    const int chh = wid >> 2;
    const int irow = (wid & 3)*32 + lid;
    const uint32_t woff = (uint32_t)(wid & 3) << 21;
    const int bh = blockIdx.y;
    const int bb = bh >> 3, h = bh & 7;
    const int i0 = blockIdx.x * 128;

    float* red = (float*)(smem + 64);

    if (wid == 0) { TC_ALLOC(sb + 0, 512); TC_RELINQ(); }
    if (tid == 0) MBAR_INIT(sb + 8, 1);
    __syncthreads();
    uint32_t tmem;
    asm volatile("ld.shared.b32 %0, [%1];" : "=r"(tmem) : "r"(sb + 0));

    const size_t bq = (size_t)bb*NPIX*CH + h*DH;
    const size_t bo = ((size_t)bb*CH + h*DH)*NPIX;

    #define LOADK(_jt, _b) do {                                              \
        int _j0 = (_jt)*128;                                                 \
        _Pragma("unroll")                                                    \
        for (int it = 0; it < 16; it++) {                                    \
            int lin = tid + it*256;                                          \
            int reg = lin >> 10;                                             \
            int j   = (lin >> 3) & 127;                                      \
            int u   = lin & 7;                                               \
            int gj  = _j0 + j;                                               \
            uint4 v = make_uint4(0,0,0,0);                                   \
            if (gj < NPIX) {                                                 \
                size_t rb = bq + (size_t)gj*CH;                              \
                const __nv_bfloat16* src =                                   \
                    (reg == 0) ? &g_kh[rb] : (reg == 1) ? &g_kl[rb] :        \
                    (reg == 2) ? &g_qh[rb] : &g_ql[rb];                      \
                v = *(const uint4*)(src + u*8);                              \
            }                                                                \
            *(uint4*)(smem + AT_KB(_b) + reg*16384 + sw_off(j, u*16)) = v;   \
        }                                                                    \
    } while (0)

    #define LOADV(_jt, _b) do {                                              \
        int _j0 = (_jt)*128;                                                 \
        _Pragma("unroll")                                                    \
        for (int it = 0; it < 8; it++) {                                     \
            int lin = tid + it*256;                                          \
            int reg = lin >> 9;                                              \
            int d   = (lin >> 3) & 63;                                       \
            int u   = lin & 7;                                               \
            int jc  = reg >> 1;                                              \
            int hl  = reg & 1;                                               \
            int gjs = _j0 + jc*64 + u*8;                                     \
            uint4 v = make_uint4(0,0,0,0);                                   \
            const __nv_bfloat16* src = hl ? g_vol : g_voh;                   \
            src += bo + (size_t)d*NPIX;                                      \
            if (gjs + 7 < NPIX) {                                            \
                v = *(const uint4*)(src + gjs);                              \
            } else if (gjs < NPIX) {                                         \
                __nv_bfloat16 tmp[8];                                        \
                _Pragma("unroll")                                            \
                for (int e = 0; e < 8; e++)                                  \
                    tmp[e] = (gjs + e < NPIX) ? src[gjs + e] : __float2bfloat16(0.f); \
                v = *(const uint4*)tmp;                                      \
            }                                                                \
            *(uint4*)(smem + AT_VB(_b) + reg*8192 + sw_off(d, u*16)) = v;    \
        }                                                                    \
    } while (0)

    #define ISSUE_S_BODY(_b) do {                                            \
        _Pragma("unroll")                                                    \
        for (int s = 0; s < 8; s++) {                                        \
            int chunk = s >> 2;                                              \
            uint64_t bh_d = mkdesc_k(sb + AT_KB(_b) + chunk*32768) + (uint64_t)((s&3)*2); \
            uint64_t bl_d = mkdesc_k(sb + AT_KB(_b) + chunk*32768 + 16384) + (uint64_t)((s&3)*2); \
            uint32_t aH = tmem + TMC_QH + s*8;                               \
            uint32_t aL = tmem + TMC_QL + s*8;                               \
            mma_f16_ts(tmem + TMC_S, aH, bh_d, IDESC_128, s != 0);           \
            mma_f16_ts(tmem + TMC_S, aH, bl_d, IDESC_128, true);             \
            mma_f16_ts(tmem + TMC_S, aL, bh_d, IDESC_128, true);             \
        }                                                                    \
    } while (0)

    #define ISSUE_PV_BODY(_b) do {                                           \
        _Pragma("unroll")                                                    \
        for (int s = 0; s < 8; s++) {                                        \
            int chunk = s >> 2;                                              \
            uint64_t bh_d = mkdesc_k(sb + AT_VB(_b) + chunk*16384) + (uint64_t)((s&3)*2); \
            uint64_t bl_d = mkdesc_k(sb + AT_VB(_b) + chunk*16384 + 8192) + (uint64_t)((s&3)*2); \
            uint32_t aH = tmem + TMC_PH + s*8;                               \
            uint32_t aL = tmem + TMC_PL + s*8;                               \
            mma_f16_ts(tmem + TMC_O, aH, bh_d, IDESC_64, s != 0);            \
            mma_f16_ts(tmem + TMC_O, aH, bl_d, IDESC_64, true);              \
            mma_f16_ts(tmem + TMC_O, aL, bh_d, IDESC_64, true);              \
        }                                                                    \
    } while (0)

    // ---- prologue ----
    {
        int gi = i0 + irow;
        uint32_t qr[32];
        const uint32_t* srcq = (chh == 0) ? (const uint32_t*)&g_qh[bq + (size_t)gi*CH]
                                          : (const uint32_t*)&g_ql[bq + (size_t)gi*CH];
        const uint32_t* srcp = (chh == 0) ? (const uint32_t*)&g_ph[((size_t)h*NPIX + gi)*DH]
                                          : (const uint32_t*)&g_pl[((size_t)h*NPIX + gi)*DH];
        uint32_t cb = (chh == 0) ? TMC_QH : TMC_QL;
        #pragma unroll
        for (int c = 0; c < 32; c++) qr[c] = (gi < NPIX) ? srcq[c] : 0u;
        STTM_X32(tmem + cb + woff, qr);
        #pragma unroll
        for (int c = 0; c < 32; c++) qr[c] = (gi < NPIX) ? srcp[c] : 0u;
        STTM_X32(tmem + cb + 32 + woff, qr);
        TC_WAIT_ST();
    }
    LOADK(0, 0);
    LOADK(1, 1);
    LOADV(0, 0);
    FENCE_ASYNC();
    TC_FENCE_BEFORE();
    __syncthreads();
    if (wid == 0) {
        TC_FENCE_AFTER();
        if (elect1()) { ISSUE_S_BODY(0); TC_COMMIT(sb + 8); }   // C0
    }

    float m = -INFINITY, l = 0.f, scale_prev = 0.f;
    float o_acc[32];
    #pragma unroll
    for (int c = 0; c < 32; c++) o_acc[c] = 0.f;

    for (int jt = 0; jt < 7; jt++) {
        const int j0 = jt * 128;
        const int buf = jt & 1, nbuf = buf ^ 1;

        // wait C_jt (covers S(jt) and PV(jt-1))
        MBAR_WAIT(sb + 8, (uint32_t)(jt & 1));
        TC_FENCE_AFTER();

        // accumulate PV(jt-1)
        if (jt >= 1) {
            uint32_t po[32];
            LDTM_X32(po, tmem + TMC_O + chh*32);
            TC_WAIT_LD();
            #pragma unroll
            for (int c = 0; c < 32; c++)
                o_acc[c] = o_acc[c]*scale_prev + __uint_as_float(po[c]);
        }

        // read S(jt)
        float sv[64];
        {
            uint32_t rr[32];
            LDTM_X32(rr, tmem + TMC_S + chh*64);
            TC_WAIT_LD();
            #pragma unroll
            for (int c = 0; c < 32; c++) sv[c] = __uint_as_float(rr[c]);
            LDTM_X32(rr, tmem + TMC_S + chh*64 + 32);
            TC_WAIT_LD();
            #pragma unroll
            for (int c = 0; c < 32; c++) sv[32+c] = __uint_as_float(rr[c]);
        }
        TC_FENCE_BEFORE();
        __syncthreads();   // all warps done reading S and O regions

        // online softmax
        float mx = -INFINITY;
        #pragma unroll
        for (int c = 0; c < 64; c++) {
            if (j0 + chh*64 + c >= NPIX) sv[c] = -INFINITY;
            mx = fmaxf(mx, sv[c]);
        }
        red[chh*128 + irow] = mx;
        __syncthreads();
        float mnew = fmaxf(m, fmaxf(red[irow], red[128 + irow]));
        float scale = __expf(m - mnew);
        m = mnew;
        float psum = 0.f;
        #pragma unroll
        for (int c = 0; c < 64; c++) {
            float p = __expf(sv[c] - mnew);
            sv[c] = p;
            psum += p;
        }
        red[256 + chh*128 + irow] = psum;
        __syncthreads();
        l = l*scale + red[256 + irow] + red[256 + 128 + irow];
        scale_prev = scale;

        // store P
        {
            uint32_t prh[32], prl[32];
            #pragma unroll
            for (int c = 0; c < 32; c++)
                split2(sv[2*c], sv[2*c+1], prh[c], prl[c]);
            STTM_X32(tmem + TMC_PH + chh*32 + woff, prh);
            STTM_X32(tmem + TMC_PL + chh*32 + woff, prl);
            TC_WAIT_ST();
        }
        TC_FENCE_BEFORE();
        __syncthreads();

        // single combined commit: PV(jt) then S(jt+1)
        if (wid == 0) {
            TC_FENCE_AFTER();
            if (elect1()) {
                ISSUE_PV_BODY(buf);
                if (jt < 6) ISSUE_S_BODY(nbuf);
                TC_COMMIT(sb + 8);     // C_{jt+1}
            }
        }

        // prefetch — overlaps the combined MMA batch
        if (jt + 2 <= 6) LOADK(jt + 2, buf);
        if (jt + 1 <= 6) LOADV(jt + 1, nbuf);
        FENCE_ASYNC();
        TC_FENCE_BEFORE();
    }

    // final: wait C7 (PV(6)), accumulate
    MBAR_WAIT(sb + 8, 1u);
    TC_FENCE_AFTER();
    {
        uint32_t po[32];
        LDTM_X32(po, tmem + TMC_O + chh*32);
        TC_WAIT_LD();
        TC_FENCE_BEFORE();
        #pragma unroll
        for (int c = 0; c < 32; c++)
            o_acc[c] = o_acc[c]*scale_prev + __uint_as_float(po[c]);
    }
    #undef LOADK
    #undef LOADV
    #undef ISSUE_S_BODY
    #undef ISSUE_PV_BODY

    // ---- epilogue: normalize, transpose via smem, coalesced store ----
    __syncthreads();
    float inv = __fdividef(1.f, l);
    float* Os = (float*)(smem + 4096);   // reuse K buf0: [d 64][i 128] stride 132
    #pragma unroll
    for (int c = 0; c < 32; c++)
        Os[(chh*32 + c)*132 + irow] = o_acc[c] * inv;
    __syncthreads();
    #pragma unroll
    for (int it = 0; it < 8; it++) {
        int lin = tid + it*256;
        int d = lin >> 5, i4 = (lin & 31)*4;
        int gi = i0 + i4;
        if (gi < NPIX) {
            float4 v = *(const float4*)&Os[d*132 + i4];
            *(float4*)&out[bo + (size_t)d*NPIX + gi] = v;
        }
    }
    __syncthreads();
    if (wid == 0) TC_DEALLOC(tmem, 512);
#else
    (void)out;
#endif
}

// ---------------------------------------------------------------------------
extern "C" void kernel_launch(void* const* d_in, const int* in_sizes, int n_in,
                              void* d_out, int out_size) {
    const float* x     = (const float*)d_in[0];
    const float* wq    = (const float*)d_in[1];
    const float* bq    = (const float*)d_in[2];
    const float* wk    = (const float*)d_in[3];
    const float* bk    = (const float*)d_in[4];
    const float* wv    = (const float*)d_in[5];
    const float* bv    = (const float*)d_in[6];
    const float* rel_h = (const float*)d_in[7];
    const float* rel_w = (const float*)d_in[8];
    float* out = (float*)d_out;

    cudaFuncSetAttribute(attn_tc_kernel,
                         cudaFuncAttributeMaxDynamicSharedMemorySize, TC_SMEM);
    cudaFuncSetAttribute(qkv_tc_kernel,
                         cudaFuncAttributeMaxDynamicSharedMemorySize, PROJ_SMEM);

    // prep
    dim3 xgrid((NPIX + 31)/32, CH/32, NB);
    split_x_kernel<<<xgrid, dim3(32, 8)>>>(x);
    split_w_kernel<<<(3*CH*CH + 255)/256, 256>>>(wq, wk, wv);
    pos_kernel<<<(HEADS*DH*NPIX + 255)/256, 256>>>(rel_h, rel_w);

    // merged tcgen05 QKV projection (2 CTAs/SM)
    dim3 pgrid(7, 8, NB);
    qkv_tc_kernel<<<pgrid, 256, PROJ_SMEM>>>(bq, bk, bv);

    // pipelined tcgen05 attention (merged commits)
    dim3 tgrid(7, NB*HEADS);
    attn_tc_kernel<<<tgrid, 256, TC_SMEM>>>(out);
}

// round 13
// speedup vs baseline: 1.1619x; 1.1619x over previous
#include <cuda_runtime.h>
#include <cuda_bf16.h>
#include <math.h>
#include <stdint.h>

#define NB    32
#define CH    512
#define WD    28
#define HDIM  28
#define NPIX  784
#define HEADS 8
#define DH    64

#if defined(__CUDA_ARCH__) && (defined(__CUDA_ARCH_FEAT_SM103_ALL) || defined(__CUDA_ARCH_FEAT_SM100_ALL))
#define HAS_TC 1
#else
#define HAS_TC 0
#endif

// ---------------- global scratch (bf16 hi/lo split) ----------------
__device__ __align__(16) __nv_bfloat16 g_xh[NB*NPIX*CH];   // x^T [b][n][c]
__device__ __align__(16) __nv_bfloat16 g_xl[NB*NPIX*CH];
__device__ __align__(16) __nv_bfloat16 g_qh[NB*NPIX*CH];   // q^T [b][n][o]
__device__ __align__(16) __nv_bfloat16 g_ql[NB*NPIX*CH];
__device__ __align__(16) __nv_bfloat16 g_kh[NB*NPIX*CH];
__device__ __align__(16) __nv_bfloat16 g_kl[NB*NPIX*CH];
__device__ __align__(16) __nv_bfloat16 g_voh[NB*CH*NPIX];  // v [b][o][n]
__device__ __align__(16) __nv_bfloat16 g_vol[NB*CH*NPIX];
__device__ __align__(16) __nv_bfloat16 g_ph[HEADS*NPIX*DH]; // pos^T [h][n][d]
__device__ __align__(16) __nv_bfloat16 g_pl[HEADS*NPIX*DH];
__device__ __align__(16) __nv_bfloat16 g_wqh[CH*CH];       // W [o][c]
__device__ __align__(16) __nv_bfloat16 g_wql[CH*CH];
__device__ __align__(16) __nv_bfloat16 g_wkh[CH*CH];
__device__ __align__(16) __nv_bfloat16 g_wkl[CH*CH];
__device__ __align__(16) __nv_bfloat16 g_wvh[CH*CH];
__device__ __align__(16) __nv_bfloat16 g_wvl[CH*CH];

// ---------------- helpers ----------------
__device__ __forceinline__ uint32_t smem_u32(const void* p) {
    uint32_t a;
    asm("{ .reg .u64 t; cvta.to.shared.u64 t, %1; cvt.u32.u64 %0, t; }"
        : "=r"(a) : "l"(p));
    return a;
}
__device__ __forceinline__ void split2(float a, float b, uint32_t& hi, uint32_t& lo) {
    __nv_bfloat16 ah = __float2bfloat16(a);
    __nv_bfloat16 bh = __float2bfloat16(b);
    __nv_bfloat16 al = __float2bfloat16(a - __bfloat162float(ah));
    __nv_bfloat16 bl = __float2bfloat16(b - __bfloat162float(bh));
    __nv_bfloat162 h2; h2.x = ah; h2.y = bh;
    __nv_bfloat162 l2; l2.x = al; l2.y = bl;
    hi = *(uint32_t*)&h2; lo = *(uint32_t*)&l2;
}
__device__ __forceinline__ void split1(float a, __nv_bfloat16& hi, __nv_bfloat16& lo) {
    hi = __float2bfloat16(a);
    lo = __float2bfloat16(a - __bfloat162float(hi));
}

#if HAS_TC
__device__ __forceinline__ uint32_t elect1() {
    uint32_t p;
    asm volatile("{\n\t.reg .pred p;\n\telect.sync _|p, 0xFFFFFFFF;\n\t"
                 "selp.b32 %0, 1, 0, p;\n\t}" : "=r"(p));
    return p;
}
#define TC_ALLOC(sa, n)   asm volatile("tcgen05.alloc.cta_group::1.sync.aligned.shared::cta.b32 [%0], %1;" :: "r"(sa), "r"(n) : "memory")
#define TC_RELINQ()       asm volatile("tcgen05.relinquish_alloc_permit.cta_group::1.sync.aligned;")
#define TC_DEALLOC(t, n)  asm volatile("tcgen05.dealloc.cta_group::1.sync.aligned.b32 %0, %1;" :: "r"(t), "r"(n))
#define TC_COMMIT(mb)     asm volatile("tcgen05.commit.cta_group::1.mbarrier::arrive::one.shared::cluster.b64 [%0];" :: "r"(mb) : "memory")
#define TC_WAIT_LD()      asm volatile("tcgen05.wait::ld.sync.aligned;" ::: "memory")
#define TC_WAIT_ST()      asm volatile("tcgen05.wait::st.sync.aligned;" ::: "memory")
#define TC_FENCE_AFTER()  asm volatile("tcgen05.fence::after_thread_sync;" ::: "memory")
#define TC_FENCE_BEFORE() asm volatile("tcgen05.fence::before_thread_sync;" ::: "memory")
#define FENCE_ASYNC()     asm volatile("fence.proxy.async.shared::cta;" ::: "memory")
#define MBAR_INIT(mb, c)  asm volatile("mbarrier.init.shared.b64 [%0], %1;" :: "r"(mb), "r"(c) : "memory")

#define MBAR_WAIT(mb, par) do {                                              \
    uint32_t _mb = (mb); uint32_t _p = (par); uint32_t _done;                \
    asm volatile("{\n\t.reg .pred p;\n\t"                                    \
        "mbarrier.try_wait.parity.acquire.cta.shared::cta.b64 p, [%1], %2;\n\t" \
        "selp.b32 %0, 1, 0, p;\n\t}"                                         \
        : "=r"(_done) : "r"(_mb), "r"(_p) : "memory");                       \
    if (!_done) {                                                            \
        asm volatile("{\n\t.reg .pred P1;\n\t"                               \
            "WL_%=:\n\t"                                                     \
            "mbarrier.try_wait.parity.acquire.cta.shared::cta.b64 P1, [%0], %1, 0x989680;\n\t" \
            "@P1 bra.uni WD_%=;\n\tbra.uni WL_%=;\n\tWD_%=:\n\t}"            \
            :: "r"(_mb), "r"(_p) : "memory");                                \
    }                                                                        \
} while (0)

#define LDTM_X32(r, addr)                                                    \
    asm volatile("tcgen05.ld.sync.aligned.32x32b.x32.b32 "                   \
        "{%0,%1,%2,%3,%4,%5,%6,%7,%8,%9,%10,%11,%12,%13,%14,%15,"            \
        "%16,%17,%18,%19,%20,%21,%22,%23,%24,%25,%26,%27,%28,%29,%30,%31}, [%32];" \
        : "=r"((r)[0]),"=r"((r)[1]),"=r"((r)[2]),"=r"((r)[3]),               \
          "=r"((r)[4]),"=r"((r)[5]),"=r"((r)[6]),"=r"((r)[7]),               \
          "=r"((r)[8]),"=r"((r)[9]),"=r"((r)[10]),"=r"((r)[11]),             \
          "=r"((r)[12]),"=r"((r)[13]),"=r"((r)[14]),"=r"((r)[15]),           \
          "=r"((r)[16]),"=r"((r)[17]),"=r"((r)[18]),"=r"((r)[19]),           \
          "=r"((r)[20]),"=r"((r)[21]),"=r"((r)[22]),"=r"((r)[23]),           \
          "=r"((r)[24]),"=r"((r)[25]),"=r"((r)[26]),"=r"((r)[27]),           \
          "=r"((r)[28]),"=r"((r)[29]),"=r"((r)[30]),"=r"((r)[31])            \
        : "r"(addr))

#define STTM_X32(addr, r)                                                    \
    asm volatile("tcgen05.st.sync.aligned.32x32b.x32.b32 [%0], "             \
        "{%1,%2,%3,%4,%5,%6,%7,%8,%9,%10,%11,%12,%13,%14,%15,%16,"           \
        "%17,%18,%19,%20,%21,%22,%23,%24,%25,%26,%27,%28,%29,%30,%31,%32};"  \
        :: "r"(addr),                                                        \
           "r"((r)[0]),"r"((r)[1]),"r"((r)[2]),"r"((r)[3]),                  \
           "r"((r)[4]),"r"((r)[5]),"r"((r)[6]),"r"((r)[7]),                  \
           "r"((r)[8]),"r"((r)[9]),"r"((r)[10]),"r"((r)[11]),                \
           "r"((r)[12]),"r"((r)[13]),"r"((r)[14]),"r"((r)[15]),              \
           "r"((r)[16]),"r"((r)[17]),"r"((r)[18]),"r"((r)[19]),              \
           "r"((r)[20]),"r"((r)[21]),"r"((r)[22]),"r"((r)[23]),              \
           "r"((r)[24]),"r"((r)[25]),"r"((r)[26]),"r"((r)[27]),              \
           "r"((r)[28]),"r"((r)[29]),"r"((r)[30]),"r"((r)[31])               \
        : "memory")

__device__ __forceinline__ void mma_f16_ts(uint32_t d, uint32_t a_tmem, uint64_t b,
                                           uint32_t idesc, bool acc) {
    uint32_t en = acc ? 1u : 0u;
    asm volatile("{\n\t.reg .pred p;\n\tsetp.ne.u32 p, %5, 0;\n\t"
        "tcgen05.mma.cta_group::1.kind::f16 [%0], [%1], %2, %3, {%4,%4,%4,%4}, p;\n\t}"
        :: "r"(d), "r"(a_tmem), "l"(b), "r"(idesc), "r"(0u), "r"(en) : "memory");
}
__device__ __forceinline__ uint64_t mkdesc_k(uint32_t addr) {   // SW128, LBO=1, SBO=64
    return ((2ull<<61)|(1ull<<46)|(64ull<<32)|(1ull<<16)) | ((uint64_t)(addr>>4)&0x3FFF);
}
#define IDESC_128 ((1u<<4)|(1u<<7)|(1u<<10)|((128/8)<<17)|((128/16)<<24))
#define IDESC_64  ((1u<<4)|(1u<<7)|(1u<<10)|((64/8)<<17)|((128/16)<<24))

__device__ __forceinline__ uint32_t sw_off(int row, int byte_in_row) {
    uint32_t off = (uint32_t)(row*128 + byte_in_row);
    return off ^ ((off >> 3) & 0x70);
}
#endif  // HAS_TC

// ---------------------------------------------------------------------------
// Prep kernels
// ---------------------------------------------------------------------------
__global__ void pos_kernel(const float* __restrict__ rel_h,
                           const float* __restrict__ rel_w) {
    int idx = blockIdx.x * 256 + threadIdx.x;
    if (idx >= HEADS*DH*NPIX) return;
    int n  = idx % NPIX;
    int hd = idx / NPIX;
    int h = hd >> 6, d = hd & 63;
    float v = rel_h[hd*HDIM + (n % HDIM)] + rel_w[hd*WD + (n / HDIM)];
    __nv_bfloat16 hi, lo;
    split1(v, hi, lo);
    size_t t = ((size_t)h*NPIX + n)*DH + d;
    g_ph[t] = hi; g_pl[t] = lo;
}

__global__ void split_x_kernel(const float* __restrict__ x) {
    __shared__ float t[32][33];
    const int bb = blockIdx.z;
    const int c0 = blockIdx.y * 32;
    const int n0 = blockIdx.x * 32;
    const int tx = threadIdx.x, ty = threadIdx.y;   // 32 x 8
    #pragma unroll
    for (int i = 0; i < 4; i++) {
        int c = c0 + ty + i*8;
        int n = n0 + tx;
        t[ty + i*8][tx] = (n < NPIX) ? x[((size_t)bb*CH + c)*NPIX + n] : 0.f;
    }
    __syncthreads();
    #pragma unroll
    for (int i = 0; i < 4; i++) {
        int n = n0 + ty + i*8;
        if (n < NPIX) {
            float v = t[tx][ty + i*8];
            __nv_bfloat16 hi, lo;
            split1(v, hi, lo);
            size_t d = ((size_t)bb*NPIX + n)*CH + c0 + tx;
            g_xh[d] = hi; g_xl[d] = lo;
        }
    }
}

__global__ void split_w_kernel(const float* __restrict__ wq,
                               const float* __restrict__ wk,
                               const float* __restrict__ wv) {
    int idx = blockIdx.x * 256 + threadIdx.x;
    if (idx >= 3*CH*CH) return;
    int m = idx / (CH*CH);
    int e = idx % (CH*CH);
    const float* src = (m == 0) ? wq : (m == 1) ? wk : wv;
    __nv_bfloat16* dh = (m == 0) ? g_wqh : (m == 1) ? g_wkh : g_wvh;
    __nv_bfloat16* dl = (m == 0) ? g_wql : (m == 1) ? g_wkl : g_wvl;
    __nv_bfloat16 hi, lo;
    split1(src[e], hi, lo);
    dh[e] = hi; dl[e] = lo;
}

// ---------------------------------------------------------------------------
// Merged QKV projection (R10/R11 proven version: N=128 o-tiles, depth-2
// pipeline, dual mbarriers, 1 CTA/SM).
// TMEM: A double-buffer 0-127 | Dq 128-255 | Dk 256-383 | Dv 384-511.
// ---------------------------------------------------------------------------
#define PB_OFF  2048
#define PCHUNK  98304
#define PROJ_SMEM (PB_OFF + 2*PCHUNK)
#define VT_STRIDE 136

__global__ __launch_bounds__(256, 1)
void qkv_tc_kernel(const float* __restrict__ bq,
                   const float* __restrict__ bk,
                   const float* __restrict__ bv) {
#if HAS_TC
    extern __shared__ char smem[];
    const uint32_t sb = smem_u32(smem);
    const int tid = threadIdx.x;
    const int wid = tid >> 5, lid = tid & 31;
    const int chh = wid >> 2;
    const int irow = (wid & 3)*32 + lid;
    const uint32_t woff = (uint32_t)(wid & 3) << 21;
    const int bb = blockIdx.z;
    const int n0 = blockIdx.x * 128;
    const int o0 = blockIdx.y * 128;

    if (wid == 0) { TC_ALLOC(sb + 0, 512); TC_RELINQ(); }
    if (tid == 0) { MBAR_INIT(sb + 8, 1); MBAR_INIT(sb + 16, 1); }
    float* bias_s = (float*)(smem + 64);
    if (tid < 128) {
        bias_s[tid]       = bq[o0 + tid];
        bias_s[128 + tid] = bk[o0 + tid];
        bias_s[256 + tid] = bv[o0 + tid];
    }
    __syncthreads();
    uint32_t tmem;
    asm volatile("ld.shared.b32 %0, [%1];" : "=r"(tmem) : "r"(sb + 0));

    const size_t xb = (size_t)bb*NPIX*CH;
    const int a_row = n0 + irow;
    const bool a_ok = (a_row < NPIX);
    const __nv_bfloat16* Asrc = (chh ? g_xl : g_xh) + xb;

    #define LOADC(ck) do {                                                   \
        int _c0 = (ck)*64, _buf = (ck)&1;                                    \
        uint32_t ar[32];                                                     \
        const uint32_t* _as = (const uint32_t*)(Asrc + (size_t)a_row*CH + _c0); \
        _Pragma("unroll")                                                    \
        for (int c = 0; c < 32; c++) ar[c] = a_ok ? _as[c] : 0u;             \
        STTM_X32(tmem + _buf*64 + chh*32 + woff, ar);                        \
        TC_WAIT_ST();                                                        \
        _Pragma("unroll")                                                    \
        for (int it = 0; it < 24; it++) {                                    \
            int lin = tid + it*256;                                          \
            int reg = lin >> 10;                                             \
            int r   = (lin >> 3) & 127;                                      \
            int u   = lin & 7;                                               \
            const __nv_bfloat16* _src =                                      \
                (reg == 0) ? g_wqh : (reg == 1) ? g_wql :                    \
                (reg == 2) ? g_wkh : (reg == 3) ? g_wkl :                    \
                (reg == 4) ? g_wvh : g_wvl;                                  \
            uint4 v = *(const uint4*)(_src + (size_t)(o0 + r)*CH + _c0 + u*8); \
            *(uint4*)(smem + PB_OFF + _buf*PCHUNK + reg*16384 + sw_off(r, u*16)) = v; \
        }                                                                    \
    } while (0)

    LOADC(0);
    FENCE_ASYNC();
    TC_FENCE_BEFORE();
    __syncthreads();

    for (int ck = 0; ck < 8; ck++) {
        int buf = ck & 1;
        if (wid == 0) {
            TC_FENCE_AFTER();
            if (elect1()) {
                #pragma unroll
                for (int t = 0; t < 3; t++) {
                    uint32_t base = sb + PB_OFF + buf*PCHUNK + t*32768;
                    uint64_t dh = mkdesc_k(base);
                    uint64_t dl = mkdesc_k(base + 16384);
                    uint32_t D = tmem + 128 + t*128;
                    #pragma unroll
                    for (int s = 0; s < 4; s++) {
                        uint32_t aH = tmem + buf*64 + s*8;
                        uint32_t aL = aH + 32;
                        mma_f16_ts(D, aH, dh + s*2, IDESC_128, !(ck == 0 && s == 0));
                        mma_f16_ts(D, aH, dl + s*2, IDESC_128, true);
                        mma_f16_ts(D, aL, dh + s*2, IDESC_128, true);
                    }
                }
                TC_COMMIT(sb + 8 + (uint32_t)(ck & 1)*8);
            }
        }
        if (ck >= 1)
            MBAR_WAIT(sb + 8 + (uint32_t)((ck - 1) & 1)*8, (uint32_t)(((ck - 1) >> 1) & 1));
        if (ck < 7) LOADC(ck + 1);
        FENCE_ASYNC();
        TC_FENCE_BEFORE();
        __syncthreads();
    }
    MBAR_WAIT(sb + 8 + 8, 1u);
    #undef LOADC
    TC_FENCE_AFTER();

    __nv_bfloat16* vsm_h = (__nv_bfloat16*)(smem + PB_OFF);
    __nv_bfloat16* vsm_l = (__nv_bfloat16*)(smem + PB_OFF + 36864);

    #pragma unroll
    for (int t = 0; t < 3; t++) {
        float sv[64];
        {
            uint32_t rr[32];
            LDTM_X32(rr, tmem + 128 + t*128 + chh*64);
            TC_WAIT_LD();
            #pragma unroll
            for (int c = 0; c < 32; c++) sv[c] = __uint_as_float(rr[c]);
            LDTM_X32(rr, tmem + 128 + t*128 + chh*64 + 32);
            TC_WAIT_LD();
            #pragma unroll
            for (int c = 0; c < 32; c++) sv[32+c] = __uint_as_float(rr[c]);
        }
        #pragma unroll
        for (int c = 0; c < 64; c++) sv[c] += bias_s[t*128 + chh*64 + c];

        if (t < 2) {
            if (a_ok) {
                uint32_t hw[32], lw[32];
                #pragma unroll
                for (int c = 0; c < 32; c++) split2(sv[2*c], sv[2*c+1], hw[c], lw[c]);
                __nv_bfloat16* OH = (t == 0) ? g_qh : g_kh;
                __nv_bfloat16* OL = (t == 0) ? g_ql : g_kl;
                size_t d = xb + (size_t)a_row*CH + o0 + chh*64;
                #pragma unroll
                for (int u = 0; u < 4; u++) {
                    *(uint4*)&OH[d + u*16]     = *(uint4*)&hw[u*8];
                    *(uint4*)&OH[d + u*16 + 8] = *(uint4*)&hw[u*8 + 4];
                    *(uint4*)&OL[d + u*16]     = *(uint4*)&lw[u*8];
                    *(uint4*)&OL[d + u*16 + 8] = *(uint4*)&lw[u*8 + 4];
                }
            }
        } else {
            __syncthreads();
            #pragma unroll
            for (int c = 0; c < 64; c++) {
                __nv_bfloat16 hi, lo;
                split1(sv[c], hi, lo);
                vsm_h[(chh*64 + c)*VT_STRIDE + irow] = hi;
                vsm_l[(chh*64 + c)*VT_STRIDE + irow] = lo;
            }
            __syncthreads();
            int o = tid >> 1, half = tid & 1;
            size_t gdst = ((size_t)bb*CH + o0 + o)*NPIX + n0;
            #pragma unroll
            for (int u = 0; u < 8; u++) {
                int n = half*64 + u*8;
                if (n0 + n < NPIX) {
                    *(uint4*)&g_voh[gdst + n] = *(const uint4*)&vsm_h[o*VT_STRIDE + n];
                    *(uint4*)&g_vol[gdst + n] = *(const uint4*)&vsm_l[o*VT_STRIDE + n];
                }
            }
        }
    }
    __syncthreads();
    if (wid == 0) TC_DEALLOC(tmem, 512);
#else
    (void)bq; (void)bk; (void)bv;
#endif
}

// ---------------------------------------------------------------------------
// Pipelined tensor-core flash attention — merged commit (R12 proven version).
// smem: ctrl [0,64) | red [64,2112) | K bufs 2x64KB @4096 | V bufs 2x32KB.
// TMEM: QH 0 | QL 64 | PH 128 | PL 192 | S 256 | O 384.
// One mbar (sb+8): commits C0 = S(0); C_{jt+1} = [PV(jt), S(jt+1)].
// ---------------------------------------------------------------------------
#define AT_KB(b) (4096 + (b)*65536)
#define AT_VB(b) (4096 + 131072 + (b)*32768)
#define TC_SMEM  (4096 + 131072 + 65536)    /* 200704 B */
#define TMC_QH 0
#define TMC_QL 64
#define TMC_PH 128
#define TMC_PL 192
#define TMC_S  256
#define TMC_O  384

__global__ __launch_bounds__(256, 1)
void attn_tc_kernel(float* __restrict__ out) {
#if HAS_TC
    extern __shared__ char smem[];
    const uint32_t sb = smem_u32(smem);
    const int tid = threadIdx.x;
    const int wid = tid >> 5, lid = tid & 31;
    const int chh = wid >> 2;
    const int irow = (wid & 3)*32 + lid;
    const uint32_t woff = (uint32_t)(wid & 3) << 21;
    const int bh = blockIdx.y;
    const int bb = bh >> 3, h = bh & 7;
    const int i0 = blockIdx.x * 128;

    float* red = (float*)(smem + 64);

    if (wid == 0) { TC_ALLOC(sb + 0, 512); TC_RELINQ(); }
    if (tid == 0) MBAR_INIT(sb + 8, 1);
    __syncthreads();
    uint32_t tmem;
    asm volatile("ld.shared.b32 %0, [%1];" : "=r"(tmem) : "r"(sb + 0));

    const size_t bq = (size_t)bb*NPIX*CH + h*DH;
    const size_t bo = ((size_t)bb*CH + h*DH)*NPIX;

    #define LOADK(_jt, _b) do {                                              \
        int _j0 = (_jt)*128;                                                 \
        _Pragma("unroll")                                                    \
        for (int it = 0; it < 16; it++) {                                    \
            int lin = tid + it*256;                                          \
            int reg = lin >> 10;                                             \
            int j   = (lin >> 3) & 127;                                      \
            int u   = lin & 7;                                               \
            int gj  = _j0 + j;                                               \
            uint4 v = make_uint4(0,0,0,0);                                   \
            if (gj < NPIX) {                                                 \
                size_t rb = bq + (size_t)gj*CH;                              \
                const __nv_bfloat16* src =                                   \
                    (reg == 0) ? &g_kh[rb] : (reg == 1) ? &g_kl[rb] :        \
                    (reg == 2) ? &g_qh[rb] : &g_ql[rb];                      \
                v = *(const uint4*)(src + u*8);                              \
            }                                                                \
            *(uint4*)(smem + AT_KB(_b) + reg*16384 + sw_off(j, u*16)) = v;   \
        }                                                                    \
    } while (0)

    #define LOADV(_jt, _b) do {                                              \
        int _j0 = (_jt)*128;                                                 \
        _Pragma("unroll")                                                    \
        for (int it = 0; it < 8; it++) {                                     \
            int lin = tid + it*256;                                          \
            int reg = lin >> 9;                                              \
            int d   = (lin >> 3) & 63;                                       \
            int u   = lin & 7;                                               \
            int jc  = reg >> 1;                                              \
            int hl  = reg & 1;                                               \
            int gjs = _j0 + jc*64 + u*8;                                     \
            uint4 v = make_uint4(0,0,0,0);                                   \
            const __nv_bfloat16* src = hl ? g_vol : g_voh;                   \
            src += bo + (size_t)d*NPIX;                                      \
            if (gjs + 7 < NPIX) {                                            \
                v = *(const uint4*)(src + gjs);                              \
            } else if (gjs < NPIX) {                                         \
                __nv_bfloat16 tmp[8];                                        \
                _Pragma("unroll")                                            \
                for (int e = 0; e < 8; e++)                                  \
                    tmp[e] = (gjs + e < NPIX) ? src[gjs + e] : __float2bfloat16(0.f); \
                v = *(const uint4*)tmp;                                      \
            }                                                                \
            *(uint4*)(smem + AT_VB(_b) + reg*8192 + sw_off(d, u*16)) = v;    \
        }                                                                    \
    } while (0)

    #define ISSUE_S_BODY(_b) do {                                            \
        _Pragma("unroll")                                                    \
        for (int s = 0; s < 8; s++) {                                        \
            int chunk = s >> 2;                                              \
            uint64_t bh_d = mkdesc_k(sb + AT_KB(_b) + chunk*32768) + (uint64_t)((s&3)*2); \
            uint64_t bl_d = mkdesc_k(sb + AT_KB(_b) + chunk*32768 + 16384) + (uint64_t)((s&3)*2); \
            uint32_t aH = tmem + TMC_QH + s*8;                               \
            uint32_t aL = tmem + TMC_QL + s*8;                               \
            mma_f16_ts(tmem + TMC_S, aH, bh_d, IDESC_128, s != 0);           \
            mma_f16_ts(tmem + TMC_S, aH, bl_d, IDESC_128, true);             \
            mma_f16_ts(tmem + TMC_S, aL, bh_d, IDESC_128, true);             \
        }                                                                    \
    } while (0)

    #define ISSUE_PV_BODY(_b) do {                                           \
        _Pragma("unroll")                                                    \
        for (int s = 0; s < 8; s++) {                                        \
            int chunk = s >> 2;                                              \
            uint64_t bh_d = mkdesc_k(sb + AT_VB(_b) + chunk*16384) + (uint64_t)((s&3)*2); \
            uint64_t bl_d = mkdesc_k(sb + AT_VB(_b) + chunk*16384 + 8192) + (uint64_t)((s&3)*2); \
            uint32_t aH = tmem + TMC_PH + s*8;                               \
            uint32_t aL = tmem + TMC_PL + s*8;                               \
            mma_f16_ts(tmem + TMC_O, aH, bh_d, IDESC_64, s != 0);            \
            mma_f16_ts(tmem + TMC_O, aH, bl_d, IDESC_64, true);              \
            mma_f16_ts(tmem + TMC_O, aL, bh_d, IDESC_64, true);              \
        }                                                                    \
    } while (0)

    // ---- prologue ----
    {
        int gi = i0 + irow;
        uint32_t qr[32];
        const uint32_t* srcq = (chh == 0) ? (const uint32_t*)&g_qh[bq + (size_t)gi*CH]
                                          : (const uint32_t*)&g_ql[bq + (size_t)gi*CH];
        const uint32_t* srcp = (chh == 0) ? (const uint32_t*)&g_ph[((size_t)h*NPIX + gi)*DH]
                                          : (const uint32_t*)&g_pl[((size_t)h*NPIX + gi)*DH];
        uint32_t cb = (chh == 0) ? TMC_QH : TMC_QL;
        #pragma unroll
        for (int c = 0; c < 32; c++) qr[c] = (gi < NPIX) ? srcq[c] : 0u;
        STTM_X32(tmem + cb + woff, qr);
        #pragma unroll
        for (int c = 0; c < 32; c++) qr[c] = (gi < NPIX) ? srcp[c] : 0u;
        STTM_X32(tmem + cb + 32 + woff, qr);
        TC_WAIT_ST();
    }
    LOADK(0, 0);
    LOADK(1, 1);
    LOADV(0, 0);
    FENCE_ASYNC();
    TC_FENCE_BEFORE();
    __syncthreads();
    if (wid == 0) {
        TC_FENCE_AFTER();
        if (elect1()) { ISSUE_S_BODY(0); TC_COMMIT(sb + 8); }   // C0
    }

    float m = -INFINITY, l = 0.f, scale_prev = 0.f;
    float o_acc[32];
    #pragma unroll
    for (int c = 0; c < 32; c++) o_acc[c] = 0.f;

    for (int jt = 0; jt < 7; jt++) {
        const int j0 = jt * 128;
        const int buf = jt & 1, nbuf = buf ^ 1;

        // wait C_jt (covers S(jt) and PV(jt-1))
        MBAR_WAIT(sb + 8, (uint32_t)(jt & 1));
        TC_FENCE_AFTER();

        // accumulate PV(jt-1)
        if (jt >= 1) {
            uint32_t po[32];
            LDTM_X32(po, tmem + TMC_O + chh*32);
            TC_WAIT_LD();
            #pragma unroll
            for (int c = 0; c < 32; c++)
                o_acc[c] = o_acc[c]*scale_prev + __uint_as_float(po[c]);
        }

        // read S(jt)
        float sv[64];
        {
            uint32_t rr[32];
            LDTM_X32(rr, tmem + TMC_S + chh*64);
            TC_WAIT_LD();
            #pragma unroll
            for (int c = 0; c < 32; c++) sv[c] = __uint_as_float(rr[c]);
            LDTM_X32(rr, tmem + TMC_S + chh*64 + 32);
            TC_WAIT_LD();
            #pragma unroll
            for (int c = 0; c < 32; c++) sv[32+c] = __uint_as_float(rr[c]);
        }
        TC_FENCE_BEFORE();
        __syncthreads();   // all warps done reading S and O regions

        // online softmax
        float mx = -INFINITY;
        #pragma unroll
        for (int c = 0; c < 64; c++) {
            if (j0 + chh*64 + c >= NPIX) sv[c] = -INFINITY;
            mx = fmaxf(mx, sv[c]);
        }
        red[chh*128 + irow] = mx;
        __syncthreads();
        float mnew = fmaxf(m, fmaxf(red[irow], red[128 + irow]));
        float scale = __expf(m - mnew);
        m = mnew;
        float psum = 0.f;
        #pragma unroll
        for (int c = 0; c < 64; c++) {
            float p = __expf(sv[c] - mnew);
            sv[c] = p;
            psum += p;
        }
        red[256 + chh*128 + irow] = psum;
        __syncthreads();
        l = l*scale + red[256 + irow] + red[256 + 128 + irow];
        scale_prev = scale;

        // store P
        {
            uint32_t prh[32], prl[32];
            #pragma unroll
            for (int c = 0; c < 32; c++)
                split2(sv[2*c], sv[2*c+1], prh[c], prl[c]);
            STTM_X32(tmem + TMC_PH + chh*32 + woff, prh);
            STTM_X32(tmem + TMC_PL + chh*32 + woff, prl);
            TC_WAIT_ST();
        }
        TC_FENCE_BEFORE();
        __syncthreads();

        // single combined commit: PV(jt) then S(jt+1)
        if (wid == 0) {
            TC_FENCE_AFTER();
            if (elect1()) {
                ISSUE_PV_BODY(buf);
                if (jt < 6) ISSUE_S_BODY(nbuf);
                TC_COMMIT(sb + 8);     // C_{jt+1}
            }
        }

        // prefetch — overlaps the combined MMA batch
        if (jt + 2 <= 6) LOADK(jt + 2, buf);
        if (jt + 1 <= 6) LOADV(jt + 1, nbuf);
        FENCE_ASYNC();
        TC_FENCE_BEFORE();
    }

    // final: wait C7 (PV(6)), accumulate
    MBAR_WAIT(sb + 8, 1u);
    TC_FENCE_AFTER();
    {
        uint32_t po[32];
        LDTM_X32(po, tmem + TMC_O + chh*32);
        TC_WAIT_LD();
        TC_FENCE_BEFORE();
        #pragma unroll
        for (int c = 0; c < 32; c++)
            o_acc[c] = o_acc[c]*scale_prev + __uint_as_float(po[c]);
    }
    #undef LOADK
    #undef LOADV
    #undef ISSUE_S_BODY
    #undef ISSUE_PV_BODY

    // ---- epilogue: normalize, transpose via smem, coalesced store ----
    __syncthreads();
    float inv = __fdividef(1.f, l);
    float* Os = (float*)(smem + 4096);   // reuse K buf0: [d 64][i 128] stride 132
    #pragma unroll
    for (int c = 0; c < 32; c++)
        Os[(chh*32 + c)*132 + irow] = o_acc[c] * inv;
    __syncthreads();
    #pragma unroll
    for (int it = 0; it < 8; it++) {
        int lin = tid + it*256;
        int d = lin >> 5, i4 = (lin & 31)*4;
        int gi = i0 + i4;
        if (gi < NPIX) {
            float4 v = *(const float4*)&Os[d*132 + i4];
            *(float4*)&out[bo + (size_t)d*NPIX + gi] = v;
        }
    }
    __syncthreads();
    if (wid == 0) TC_DEALLOC(tmem, 512);
#else
    (void)out;
#endif
}

// ---------------------------------------------------------------------------
extern "C" void kernel_launch(void* const* d_in, const int* in_sizes, int n_in,
                              void* d_out, int out_size) {
    const float* x     = (const float*)d_in[0];
    const float* wq    = (const float*)d_in[1];
    const float* bq    = (const float*)d_in[2];
    const float* wk    = (const float*)d_in[3];
    const float* bk    = (const float*)d_in[4];
    const float* wv    = (const float*)d_in[5];
    const float* bv    = (const float*)d_in[6];
    const float* rel_h = (const float*)d_in[7];
    const float* rel_w = (const float*)d_in[8];
    float* out = (float*)d_out;

    cudaFuncSetAttribute(attn_tc_kernel,
                         cudaFuncAttributeMaxDynamicSharedMemorySize, TC_SMEM);
    cudaFuncSetAttribute(qkv_tc_kernel,
                         cudaFuncAttributeMaxDynamicSharedMemorySize, PROJ_SMEM);

    // prep
    dim3 xgrid((NPIX + 31)/32, CH/32, NB);
    split_x_kernel<<<xgrid, dim3(32, 8)>>>(x);
    split_w_kernel<<<(3*CH*CH + 255)/256, 256>>>(wq, wk, wv);
    pos_kernel<<<(HEADS*DH*NPIX + 255)/256, 256>>>(rel_h, rel_w);

    // merged tcgen05 QKV projection (R10/R11 proven config)
    dim3 pgrid(7, 4, NB);
    qkv_tc_kernel<<<pgrid, 256, PROJ_SMEM>>>(bq, bk, bv);

    // pipelined tcgen05 attention (merged commits)
    dim3 tgrid(7, NB*HEADS);
    attn_tc_kernel<<<tgrid, 256, TC_SMEM>>>(out);
}

// round 14
// speedup vs baseline: 1.1622x; 1.0002x over previous
#include <cuda_runtime.h>
#include <cuda_bf16.h>
#include <math.h>
#include <stdint.h>

#define NB    32
#define CH    512
#define WD    28
#define HDIM  28
#define NPIX  784
#define HEADS 8
#define DH    64

#if defined(__CUDA_ARCH__) && (defined(__CUDA_ARCH_FEAT_SM103_ALL) || defined(__CUDA_ARCH_FEAT_SM100_ALL))
#define HAS_TC 1
#else
#define HAS_TC 0
#endif

// ---------------- global scratch (bf16 hi/lo split) ----------------
__device__ __align__(16) __nv_bfloat16 g_xh[NB*NPIX*CH];   // x^T [b][n][c]
__device__ __align__(16) __nv_bfloat16 g_xl[NB*NPIX*CH];
__device__ __align__(16) __nv_bfloat16 g_qh[NB*NPIX*CH];   // q^T [b][n][o]
__device__ __align__(16) __nv_bfloat16 g_ql[NB*NPIX*CH];
__device__ __align__(16) __nv_bfloat16 g_kh[NB*NPIX*CH];
__device__ __align__(16) __nv_bfloat16 g_kl[NB*NPIX*CH];
__device__ __align__(16) __nv_bfloat16 g_voh[NB*CH*NPIX];  // v [b][o][n]
__device__ __align__(16) __nv_bfloat16 g_vol[NB*CH*NPIX];
__device__ __align__(16) __nv_bfloat16 g_ph[HEADS*NPIX*DH]; // pos^T [h][n][d]
__device__ __align__(16) __nv_bfloat16 g_pl[HEADS*NPIX*DH];
__device__ __align__(16) __nv_bfloat16 g_wqh[CH*CH];       // W [o][c]
__device__ __align__(16) __nv_bfloat16 g_wql[CH*CH];
__device__ __align__(16) __nv_bfloat16 g_wkh[CH*CH];
__device__ __align__(16) __nv_bfloat16 g_wkl[CH*CH];
__device__ __align__(16) __nv_bfloat16 g_wvh[CH*CH];
__device__ __align__(16) __nv_bfloat16 g_wvl[CH*CH];

// ---------------- helpers ----------------
__device__ __forceinline__ uint32_t smem_u32(const void* p) {
    uint32_t a;
    asm("{ .reg .u64 t; cvta.to.shared.u64 t, %1; cvt.u32.u64 %0, t; }"
        : "=r"(a) : "l"(p));
    return a;
}
__device__ __forceinline__ void split2(float a, float b, uint32_t& hi, uint32_t& lo) {
    __nv_bfloat16 ah = __float2bfloat16(a);
    __nv_bfloat16 bh = __float2bfloat16(b);
    __nv_bfloat16 al = __float2bfloat16(a - __bfloat162float(ah));
    __nv_bfloat16 bl = __float2bfloat16(b - __bfloat162float(bh));
    __nv_bfloat162 h2; h2.x = ah; h2.y = bh;
    __nv_bfloat162 l2; l2.x = al; l2.y = bl;
    hi = *(uint32_t*)&h2; lo = *(uint32_t*)&l2;
}
__device__ __forceinline__ void split1(float a, __nv_bfloat16& hi, __nv_bfloat16& lo) {
    hi = __float2bfloat16(a);
    lo = __float2bfloat16(a - __bfloat162float(hi));
}

#if HAS_TC
__device__ __forceinline__ uint32_t elect1() {
    uint32_t p;
    asm volatile("{\n\t.reg .pred p;\n\telect.sync _|p, 0xFFFFFFFF;\n\t"
                 "selp.b32 %0, 1, 0, p;\n\t}" : "=r"(p));
    return p;
}
#define TC_ALLOC(sa, n)   asm volatile("tcgen05.alloc.cta_group::1.sync.aligned.shared::cta.b32 [%0], %1;" :: "r"(sa), "r"(n) : "memory")
#define TC_RELINQ()       asm volatile("tcgen05.relinquish_alloc_permit.cta_group::1.sync.aligned;")
#define TC_DEALLOC(t, n)  asm volatile("tcgen05.dealloc.cta_group::1.sync.aligned.b32 %0, %1;" :: "r"(t), "r"(n))
#define TC_COMMIT(mb)     asm volatile("tcgen05.commit.cta_group::1.mbarrier::arrive::one.shared::cluster.b64 [%0];" :: "r"(mb) : "memory")
#define TC_WAIT_LD()      asm volatile("tcgen05.wait::ld.sync.aligned;" ::: "memory")
#define TC_WAIT_ST()      asm volatile("tcgen05.wait::st.sync.aligned;" ::: "memory")
#define TC_FENCE_AFTER()  asm volatile("tcgen05.fence::after_thread_sync;" ::: "memory")
#define TC_FENCE_BEFORE() asm volatile("tcgen05.fence::before_thread_sync;" ::: "memory")
#define FENCE_ASYNC()     asm volatile("fence.proxy.async.shared::cta;" ::: "memory")
#define MBAR_INIT(mb, c)  asm volatile("mbarrier.init.shared.b64 [%0], %1;" :: "r"(mb), "r"(c) : "memory")

#define MBAR_WAIT(mb, par) do {                                              \
    uint32_t _mb = (mb); uint32_t _p = (par); uint32_t _done;                \
    asm volatile("{\n\t.reg .pred p;\n\t"                                    \
        "mbarrier.try_wait.parity.acquire.cta.shared::cta.b64 p, [%1], %2;\n\t" \
        "selp.b32 %0, 1, 0, p;\n\t}"                                         \
        : "=r"(_done) : "r"(_mb), "r"(_p) : "memory");                       \
    if (!_done) {                                                            \
        asm volatile("{\n\t.reg .pred P1;\n\t"                               \
            "WL_%=:\n\t"                                                     \
            "mbarrier.try_wait.parity.acquire.cta.shared::cta.b64 P1, [%0], %1, 0x989680;\n\t" \
            "@P1 bra.uni WD_%=;\n\tbra.uni WL_%=;\n\tWD_%=:\n\t}"            \
            :: "r"(_mb), "r"(_p) : "memory");                                \
    }                                                                        \
} while (0)

#define LDTM_X32(r, addr)                                                    \
    asm volatile("tcgen05.ld.sync.aligned.32x32b.x32.b32 "                   \
        "{%0,%1,%2,%3,%4,%5,%6,%7,%8,%9,%10,%11,%12,%13,%14,%15,"            \
        "%16,%17,%18,%19,%20,%21,%22,%23,%24,%25,%26,%27,%28,%29,%30,%31}, [%32];" \
        : "=r"((r)[0]),"=r"((r)[1]),"=r"((r)[2]),"=r"((r)[3]),               \
          "=r"((r)[4]),"=r"((r)[5]),"=r"((r)[6]),"=r"((r)[7]),               \
          "=r"((r)[8]),"=r"((r)[9]),"=r"((r)[10]),"=r"((r)[11]),             \
          "=r"((r)[12]),"=r"((r)[13]),"=r"((r)[14]),"=r"((r)[15]),           \
          "=r"((r)[16]),"=r"((r)[17]),"=r"((r)[18]),"=r"((r)[19]),           \
          "=r"((r)[20]),"=r"((r)[21]),"=r"((r)[22]),"=r"((r)[23]),           \
          "=r"((r)[24]),"=r"((r)[25]),"=r"((r)[26]),"=r"((r)[27]),           \
          "=r"((r)[28]),"=r"((r)[29]),"=r"((r)[30]),"=r"((r)[31])            \
        : "r"(addr))

#define STTM_X32(addr, r)                                                    \
    asm volatile("tcgen05.st.sync.aligned.32x32b.x32.b32 [%0], "             \
        "{%1,%2,%3,%4,%5,%6,%7,%8,%9,%10,%11,%12,%13,%14,%15,%16,"           \
        "%17,%18,%19,%20,%21,%22,%23,%24,%25,%26,%27,%28,%29,%30,%31,%32};"  \
        :: "r"(addr),                                                        \
           "r"((r)[0]),"r"((r)[1]),"r"((r)[2]),"r"((r)[3]),                  \
           "r"((r)[4]),"r"((r)[5]),"r"((r)[6]),"r"((r)[7]),                  \
           "r"((r)[8]),"r"((r)[9]),"r"((r)[10]),"r"((r)[11]),                \
           "r"((r)[12]),"r"((r)[13]),"r"((r)[14]),"r"((r)[15]),              \
           "r"((r)[16]),"r"((r)[17]),"r"((r)[18]),"r"((r)[19]),              \
           "r"((r)[20]),"r"((r)[21]),"r"((r)[22]),"r"((r)[23]),              \
           "r"((r)[24]),"r"((r)[25]),"r"((r)[26]),"r"((r)[27]),              \
           "r"((r)[28]),"r"((r)[29]),"r"((r)[30]),"r"((r)[31])               \
        : "memory")

__device__ __forceinline__ void mma_f16_ts(uint32_t d, uint32_t a_tmem, uint64_t b,
                                           uint32_t idesc, bool acc) {
    uint32_t en = acc ? 1u : 0u;
    asm volatile("{\n\t.reg .pred p;\n\tsetp.ne.u32 p, %5, 0;\n\t"
        "tcgen05.mma.cta_group::1.kind::f16 [%0], [%1], %2, %3, {%4,%4,%4,%4}, p;\n\t}"
        :: "r"(d), "r"(a_tmem), "l"(b), "r"(idesc), "r"(0u), "r"(en) : "memory");
}
__device__ __forceinline__ uint64_t mkdesc_k(uint32_t addr) {   // SW128, LBO=1, SBO=64
    return ((2ull<<61)|(1ull<<46)|(64ull<<32)|(1ull<<16)) | ((uint64_t)(addr>>4)&0x3FFF);
}
#define IDESC_128 ((1u<<4)|(1u<<7)|(1u<<10)|((128/8)<<17)|((128/16)<<24))
#define IDESC_64  ((1u<<4)|(1u<<7)|(1u<<10)|((64/8)<<17)|((128/16)<<24))

__device__ __forceinline__ uint32_t sw_off(int row, int byte_in_row) {
    uint32_t off = (uint32_t)(row*128 + byte_in_row);
    return off ^ ((off >> 3) & 0x70);
}
#endif  // HAS_TC

// ---------------------------------------------------------------------------
// Prep kernels
// ---------------------------------------------------------------------------
__global__ void pos_kernel(const float* __restrict__ rel_h,
                           const float* __restrict__ rel_w) {
    int idx = blockIdx.x * 256 + threadIdx.x;
    if (idx >= HEADS*DH*NPIX) return;
    int n  = idx % NPIX;
    int hd = idx / NPIX;
    int h = hd >> 6, d = hd & 63;
    float v = rel_h[hd*HDIM + (n % HDIM)] + rel_w[hd*WD + (n / HDIM)];
    __nv_bfloat16 hi, lo;
    split1(v, hi, lo);
    size_t t = ((size_t)h*NPIX + n)*DH + d;
    g_ph[t] = hi; g_pl[t] = lo;
}

__global__ void split_x_kernel(const float* __restrict__ x) {
    __shared__ float t[32][33];
    const int bb = blockIdx.z;
    const int c0 = blockIdx.y * 32;
    const int n0 = blockIdx.x * 32;
    const int tx = threadIdx.x, ty = threadIdx.y;   // 32 x 8
    #pragma unroll
    for (int i = 0; i < 4; i++) {
        int c = c0 + ty + i*8;
        int n = n0 + tx;
        t[ty + i*8][tx] = (n < NPIX) ? x[((size_t)bb*CH + c)*NPIX + n] : 0.f;
    }
    __syncthreads();
    #pragma unroll
    for (int i = 0; i < 4; i++) {
        int n = n0 + ty + i*8;
        if (n < NPIX) {
            float v = t[tx][ty + i*8];
            __nv_bfloat16 hi, lo;
            split1(v, hi, lo);
            size_t d = ((size_t)bb*NPIX + n)*CH + c0 + tx;
            g_xh[d] = hi; g_xl[d] = lo;
        }
    }
}

__global__ void split_w_kernel(const float* __restrict__ wq,
                               const float* __restrict__ wk,
                               const float* __restrict__ wv) {
    int idx = blockIdx.x * 256 + threadIdx.x;
    if (idx >= 3*CH*CH) return;
    int m = idx / (CH*CH);
    int e = idx % (CH*CH);
    const float* src = (m == 0) ? wq : (m == 1) ? wk : wv;
    __nv_bfloat16* dh = (m == 0) ? g_wqh : (m == 1) ? g_wkh : g_wvh;
    __nv_bfloat16* dl = (m == 0) ? g_wql : (m == 1) ? g_wkl : g_wvl;
    __nv_bfloat16 hi, lo;
    split1(src[e], hi, lo);
    dh[e] = hi; dl[e] = lo;
}

// ---------------------------------------------------------------------------
// Merged QKV projection (R10/R11 proven version: N=128 o-tiles, depth-2
// pipeline, dual mbarriers, 1 CTA/SM).
// TMEM: A double-buffer 0-127 | Dq 128-255 | Dk 256-383 | Dv 384-511.
// ---------------------------------------------------------------------------
#define PB_OFF  2048
#define PCHUNK  98304
#define PROJ_SMEM (PB_OFF + 2*PCHUNK)
#define VT_STRIDE 136

__global__ __launch_bounds__(256, 1)
void qkv_tc_kernel(const float* __restrict__ bq,
                   const float* __restrict__ bk,
                   const float* __restrict__ bv) {
#if HAS_TC
    extern __shared__ char smem[];
    const uint32_t sb = smem_u32(smem);
    const int tid = threadIdx.x;
    const int wid = tid >> 5, lid = tid & 31;
    const int chh = wid >> 2;
    const int irow = (wid & 3)*32 + lid;
    const uint32_t woff = (uint32_t)(wid & 3) << 21;
    const int bb = blockIdx.z;
    const int n0 = blockIdx.x * 128;
    const int o0 = blockIdx.y * 128;

    if (wid == 0) { TC_ALLOC(sb + 0, 512); TC_RELINQ(); }
    if (tid == 0) { MBAR_INIT(sb + 8, 1); MBAR_INIT(sb + 16, 1); }
    float* bias_s = (float*)(smem + 64);
    if (tid < 128) {
        bias_s[tid]       = bq[o0 + tid];
        bias_s[128 + tid] = bk[o0 + tid];
        bias_s[256 + tid] = bv[o0 + tid];
    }
    __syncthreads();
    uint32_t tmem;
    asm volatile("ld.shared.b32 %0, [%1];" : "=r"(tmem) : "r"(sb + 0));

    const size_t xb = (size_t)bb*NPIX*CH;
    const int a_row = n0 + irow;
    const bool a_ok = (a_row < NPIX);
    const __nv_bfloat16* Asrc = (chh ? g_xl : g_xh) + xb;

    #define LOADC(ck) do {                                                   \
        int _c0 = (ck)*64, _buf = (ck)&1;                                    \
        uint32_t ar[32];                                                     \
        const uint32_t* _as = (const uint32_t*)(Asrc + (size_t)a_row*CH + _c0); \
        _Pragma("unroll")                                                    \
        for (int c = 0; c < 32; c++) ar[c] = a_ok ? _as[c] : 0u;             \
        STTM_X32(tmem + _buf*64 + chh*32 + woff, ar);                        \
        TC_WAIT_ST();                                                        \
        _Pragma("unroll")                                                    \
        for (int it = 0; it < 24; it++) {                                    \
            int lin = tid + it*256;                                          \
            int reg = lin >> 10;                                             \
            int r   = (lin >> 3) & 127;                                      \
            int u   = lin & 7;                                               \
            const __nv_bfloat16* _src =                                      \
                (reg == 0) ? g_wqh : (reg == 1) ? g_wql :                    \
                (reg == 2) ? g_wkh : (reg == 3) ? g_wkl :                    \
                (reg == 4) ? g_wvh : g_wvl;                                  \
            uint4 v = *(const uint4*)(_src + (size_t)(o0 + r)*CH + _c0 + u*8); \
            *(uint4*)(smem + PB_OFF + _buf*PCHUNK + reg*16384 + sw_off(r, u*16)) = v; \
        }                                                                    \
    } while (0)

    LOADC(0);
    FENCE_ASYNC();
    TC_FENCE_BEFORE();
    __syncthreads();

    for (int ck = 0; ck < 8; ck++) {
        int buf = ck & 1;
        if (wid == 0) {
            TC_FENCE_AFTER();
            if (elect1()) {
                #pragma unroll
                for (int t = 0; t < 3; t++) {
                    uint32_t base = sb + PB_OFF + buf*PCHUNK + t*32768;
                    uint64_t dh = mkdesc_k(base);
                    uint64_t dl = mkdesc_k(base + 16384);
                    uint32_t D = tmem + 128 + t*128;
                    #pragma unroll
                    for (int s = 0; s < 4; s++) {
                        uint32_t aH = tmem + buf*64 + s*8;
                        uint32_t aL = aH + 32;
                        mma_f16_ts(D, aH, dh + s*2, IDESC_128, !(ck == 0 && s == 0));
                        mma_f16_ts(D, aH, dl + s*2, IDESC_128, true);
                        mma_f16_ts(D, aL, dh + s*2, IDESC_128, true);
                    }
                }
                TC_COMMIT(sb + 8 + (uint32_t)(ck & 1)*8);
            }
        }
        if (ck >= 1)
            MBAR_WAIT(sb + 8 + (uint32_t)((ck - 1) & 1)*8, (uint32_t)(((ck - 1) >> 1) & 1));
        if (ck < 7) LOADC(ck + 1);
        FENCE_ASYNC();
        TC_FENCE_BEFORE();
        __syncthreads();
    }
    MBAR_WAIT(sb + 8 + 8, 1u);
    #undef LOADC
    TC_FENCE_AFTER();

    __nv_bfloat16* vsm_h = (__nv_bfloat16*)(smem + PB_OFF);
    __nv_bfloat16* vsm_l = (__nv_bfloat16*)(smem + PB_OFF + 36864);

    #pragma unroll
    for (int t = 0; t < 3; t++) {
        float sv[64];
        {
            uint32_t rr[32];
            LDTM_X32(rr, tmem + 128 + t*128 + chh*64);
            TC_WAIT_LD();
            #pragma unroll
            for (int c = 0; c < 32; c++) sv[c] = __uint_as_float(rr[c]);
            LDTM_X32(rr, tmem + 128 + t*128 + chh*64 + 32);
            TC_WAIT_LD();
            #pragma unroll
            for (int c = 0; c < 32; c++) sv[32+c] = __uint_as_float(rr[c]);
        }
        #pragma unroll
        for (int c = 0; c < 64; c++) sv[c] += bias_s[t*128 + chh*64 + c];

        if (t < 2) {
            if (a_ok) {
                uint32_t hw[32], lw[32];
                #pragma unroll
                for (int c = 0; c < 32; c++) split2(sv[2*c], sv[2*c+1], hw[c], lw[c]);
                __nv_bfloat16* OH = (t == 0) ? g_qh : g_kh;
                __nv_bfloat16* OL = (t == 0) ? g_ql : g_kl;
                size_t d = xb + (size_t)a_row*CH + o0 + chh*64;
                #pragma unroll
                for (int u = 0; u < 4; u++) {
                    *(uint4*)&OH[d + u*16]     = *(uint4*)&hw[u*8];
                    *(uint4*)&OH[d + u*16 + 8] = *(uint4*)&hw[u*8 + 4];
                    *(uint4*)&OL[d + u*16]     = *(uint4*)&lw[u*8];
                    *(uint4*)&OL[d + u*16 + 8] = *(uint4*)&lw[u*8 + 4];
                }
            }
        } else {
            __syncthreads();
            #pragma unroll
            for (int c = 0; c < 64; c++) {
                __nv_bfloat16 hi, lo;
                split1(sv[c], hi, lo);
                vsm_h[(chh*64 + c)*VT_STRIDE + irow] = hi;
                vsm_l[(chh*64 + c)*VT_STRIDE + irow] = lo;
            }
            __syncthreads();
            int o = tid >> 1, half = tid & 1;
            size_t gdst = ((size_t)bb*CH + o0 + o)*NPIX + n0;
            #pragma unroll
            for (int u = 0; u < 8; u++) {
                int n = half*64 + u*8;
                if (n0 + n < NPIX) {
                    *(uint4*)&g_voh[gdst + n] = *(const uint4*)&vsm_h[o*VT_STRIDE + n];
                    *(uint4*)&g_vol[gdst + n] = *(const uint4*)&vsm_l[o*VT_STRIDE + n];
                }
            }
        }
    }
    __syncthreads();
    if (wid == 0) TC_DEALLOC(tmem, 512);
#else
    (void)bq; (void)bk; (void)bv;
#endif
}

// ---------------------------------------------------------------------------
// Pipelined tensor-core flash attention — merged commit (R12 proven version).
// smem: ctrl [0,64) | red [64,2112) | K bufs 2x64KB @4096 | V bufs 2x32KB.
// TMEM: QH 0 | QL 64 | PH 128 | PL 192 | S 256 | O 384.
// One mbar (sb+8): commits C0 = S(0); C_{jt+1} = [PV(jt), S(jt+1)].
// ---------------------------------------------------------------------------
#define AT_KB(b) (4096 + (b)*65536)
#define AT_VB(b) (4096 + 131072 + (b)*32768)
#define TC_SMEM  (4096 + 131072 + 65536)    /* 200704 B */
#define TMC_QH 0
#define TMC_QL 64
#define TMC_PH 128
#define TMC_PL 192
#define TMC_S  256
#define TMC_O  384

__global__ __launch_bounds__(256, 1)
void attn_tc_kernel(float* __restrict__ out) {
#if HAS_TC
    extern __shared__ char smem[];
    const uint32_t sb = smem_u32(smem);
    const int tid = threadIdx.x;
    const int wid = tid >> 5, lid = tid & 31;
    const int chh = wid >> 2;
    const int irow = (wid & 3)*32 + lid;
    const uint32_t woff = (uint32_t)(wid & 3) << 21;
    const int bh = blockIdx.y;
    const int bb = bh >> 3, h = bh & 7;
    const int i0 = blockIdx.x * 128;

    float* red = (float*)(smem + 64);

    if (wid == 0) { TC_ALLOC(sb + 0, 512); TC_RELINQ(); }
    if (tid == 0) MBAR_INIT(sb + 8, 1);
    __syncthreads();
    uint32_t tmem;
    asm volatile("ld.shared.b32 %0, [%1];" : "=r"(tmem) : "r"(sb + 0));

    const size_t bq = (size_t)bb*NPIX*CH + h*DH;
    const size_t bo = ((size_t)bb*CH + h*DH)*NPIX;

    #define LOADK(_jt, _b) do {                                              \
        int _j0 = (_jt)*128;                                                 \
        _Pragma("unroll")                                                    \
        for (int it = 0; it < 16; it++) {                                    \
            int lin = tid + it*256;                                          \
            int reg = lin >> 10;                                             \
            int j   = (lin >> 3) & 127;                                      \
            int u   = lin & 7;                                               \
            int gj  = _j0 + j;                                               \
            uint4 v = make_uint4(0,0,0,0);                                   \
            if (gj < NPIX) {                                                 \
                size_t rb = bq + (size_t)gj*CH;                              \
                const __nv_bfloat16* src =                                   \
                    (reg == 0) ? &g_kh[rb] : (reg == 1) ? &g_kl[rb] :        \
                    (reg == 2) ? &g_qh[rb] : &g_ql[rb];                      \
                v = *(const uint4*)(src + u*8);                              \
            }                                                                \
            *(uint4*)(smem + AT_KB(_b) + reg*16384 + sw_off(j, u*16)) = v;   \
        }                                                                    \
    } while (0)

    #define LOADV(_jt, _b) do {                                              \
        int _j0 = (_jt)*128;                                                 \
        _Pragma("unroll")                                                    \
        for (int it = 0; it < 8; it++) {                                     \
            int lin = tid + it*256;                                          \
            int reg = lin >> 9;                                              \
            int d   = (lin >> 3) & 63;                                       \
            int u   = lin & 7;                                               \
            int jc  = reg >> 1;                                              \
            int hl  = reg & 1;                                               \
            int gjs = _j0 + jc*64 + u*8;                                     \
            uint4 v = make_uint4(0,0,0,0);                                   \
            const __nv_bfloat16* src = hl ? g_vol : g_voh;                   \
            src += bo + (size_t)d*NPIX;                                      \
            if (gjs + 7 < NPIX) {                                            \
                v = *(const uint4*)(src + gjs);                              \
            } else if (gjs < NPIX) {                                         \
                __nv_bfloat16 tmp[8];                                        \
                _Pragma("unroll")                                            \
                for (int e = 0; e < 8; e++)                                  \
                    tmp[e] = (gjs + e < NPIX) ? src[gjs + e] : __float2bfloat16(0.f); \
                v = *(const uint4*)tmp;                                      \
            }                                                                \
            *(uint4*)(smem + AT_VB(_b) + reg*8192 + sw_off(d, u*16)) = v;    \
        }                                                                    \
    } while (0)

    #define ISSUE_S_BODY(_b) do {                                            \
        _Pragma("unroll")                                                    \
        for (int s = 0; s < 8; s++) {                                        \
            int chunk = s >> 2;                                              \
            uint64_t bh_d = mkdesc_k(sb + AT_KB(_b) + chunk*32768) + (uint64_t)((s&3)*2); \
            uint64_t bl_d = mkdesc_k(sb + AT_KB(_b) + chunk*32768 + 16384) + (uint64_t)((s&3)*2); \
            uint32_t aH = tmem + TMC_QH + s*8;                               \
            uint32_t aL = tmem + TMC_QL + s*8;                               \
            mma_f16_ts(tmem + TMC_S, aH, bh_d, IDESC_128, s != 0);           \
            mma_f16_ts(tmem + TMC_S, aH, bl_d, IDESC_128, true);             \
            mma_f16_ts(tmem + TMC_S, aL, bh_d, IDESC_128, true);             \
        }                                                                    \
    } while (0)

    #define ISSUE_PV_BODY(_b) do {                                           \
        _Pragma("unroll")                                                    \
        for (int s = 0; s < 8; s++) {                                        \
            int chunk = s >> 2;                                              \
            uint64_t bh_d = mkdesc_k(sb + AT_VB(_b) + chunk*16384) + (uint64_t)((s&3)*2); \
            uint64_t bl_d = mkdesc_k(sb + AT_VB(_b) + chunk*16384 + 8192) + (uint64_t)((s&3)*2); \
            uint32_t aH = tmem + TMC_PH + s*8;                               \
            uint32_t aL = tmem + TMC_PL + s*8;                               \
            mma_f16_ts(tmem + TMC_O, aH, bh_d, IDESC_64, s != 0);            \
            mma_f16_ts(tmem + TMC_O, aH, bl_d, IDESC_64, true);              \
            mma_f16_ts(tmem + TMC_O, aL, bh_d, IDESC_64, true);              \
        }                                                                    \
    } while (0)

    // ---- prologue ----
    {
        int gi = i0 + irow;
        uint32_t qr[32];
        const uint32_t* srcq = (chh == 0) ? (const uint32_t*)&g_qh[bq + (size_t)gi*CH]
                                          : (const uint32_t*)&g_ql[bq + (size_t)gi*CH];
        const uint32_t* srcp = (chh == 0) ? (const uint32_t*)&g_ph[((size_t)h*NPIX + gi)*DH]
                                          : (const uint32_t*)&g_pl[((size_t)h*NPIX + gi)*DH];
        uint32_t cb = (chh == 0) ? TMC_QH : TMC_QL;
        #pragma unroll
        for (int c = 0; c < 32; c++) qr[c] = (gi < NPIX) ? srcq[c] : 0u;
        STTM_X32(tmem + cb + woff, qr);
        #pragma unroll
        for (int c = 0; c < 32; c++) qr[c] = (gi < NPIX) ? srcp[c] : 0u;
        STTM_X32(tmem + cb + 32 + woff, qr);
        TC_WAIT_ST();
    }
    LOADK(0, 0);
    LOADK(1, 1);
    LOADV(0, 0);
    FENCE_ASYNC();
    TC_FENCE_BEFORE();
    __syncthreads();
    if (wid == 0) {
        TC_FENCE_AFTER();
        if (elect1()) { ISSUE_S_BODY(0); TC_COMMIT(sb + 8); }   // C0
    }

    float m = -INFINITY, l = 0.f, scale_prev = 0.f;
    float o_acc[32];
    #pragma unroll
    for (int c = 0; c < 32; c++) o_acc[c] = 0.f;

    for (int jt = 0; jt < 7; jt++) {
        const int j0 = jt * 128;
        const int buf = jt & 1, nbuf = buf ^ 1;

        // wait C_jt (covers S(jt) and PV(jt-1))
        MBAR_WAIT(sb + 8, (uint32_t)(jt & 1));
        TC_FENCE_AFTER();

        // accumulate PV(jt-1)
        if (jt >= 1) {
            uint32_t po[32];
            LDTM_X32(po, tmem + TMC_O + chh*32);
            TC_WAIT_LD();
            #pragma unroll
            for (int c = 0; c < 32; c++)
                o_acc[c] = o_acc[c]*scale_prev + __uint_as_float(po[c]);
        }

        // read S(jt)
        float sv[64];
        {
            uint32_t rr[32];
            LDTM_X32(rr, tmem + TMC_S + chh*64);
            TC_WAIT_LD();
            #pragma unroll
            for (int c = 0; c < 32; c++) sv[c] = __uint_as_float(rr[c]);
            LDTM_X32(rr, tmem + TMC_S + chh*64 + 32);
            TC_WAIT_LD();
            #pragma unroll
            for (int c = 0; c < 32; c++) sv[32+c] = __uint_as_float(rr[c]);
        }
        TC_FENCE_BEFORE();
        __syncthreads();   // all warps done reading S and O regions

        // online softmax
        float mx = -INFINITY;
        #pragma unroll
        for (int c = 0; c < 64; c++) {
            if (j0 + chh*64 + c >= NPIX) sv[c] = -INFINITY;
            mx = fmaxf(mx, sv[c]);
        }
        red[chh*128 + irow] = mx;
        __syncthreads();
        float mnew = fmaxf(m, fmaxf(red[irow], red[128 + irow]));
        float scale = __expf(m - mnew);
        m = mnew;
        float psum = 0.f;
        #pragma unroll
        for (int c = 0; c < 64; c++) {
            float p = __expf(sv[c] - mnew);
            sv[c] = p;
            psum += p;
        }
        red[256 + chh*128 + irow] = psum;
        __syncthreads();
        l = l*scale + red[256 + irow] + red[256 + 128 + irow];
        scale_prev = scale;

        // store P
        {
            uint32_t prh[32], prl[32];
            #pragma unroll
            for (int c = 0; c < 32; c++)
                split2(sv[2*c], sv[2*c+1], prh[c], prl[c]);
            STTM_X32(tmem + TMC_PH + chh*32 + woff, prh);
            STTM_X32(tmem + TMC_PL + chh*32 + woff, prl);
            TC_WAIT_ST();
        }
        TC_FENCE_BEFORE();
        __syncthreads();

        // single combined commit: PV(jt) then S(jt+1)
        if (wid == 0) {
            TC_FENCE_AFTER();
            if (elect1()) {
                ISSUE_PV_BODY(buf);
                if (jt < 6) ISSUE_S_BODY(nbuf);
                TC_COMMIT(sb + 8);     // C_{jt+1}
            }
        }

        // prefetch — overlaps the combined MMA batch
        if (jt + 2 <= 6) LOADK(jt + 2, buf);
        if (jt + 1 <= 6) LOADV(jt + 1, nbuf);
        FENCE_ASYNC();
        TC_FENCE_BEFORE();
    }

    // final: wait C7 (PV(6)), accumulate
    MBAR_WAIT(sb + 8, 1u);
    TC_FENCE_AFTER();
    {
        uint32_t po[32];
        LDTM_X32(po, tmem + TMC_O + chh*32);
        TC_WAIT_LD();
        TC_FENCE_BEFORE();
        #pragma unroll
        for (int c = 0; c < 32; c++)
            o_acc[c] = o_acc[c]*scale_prev + __uint_as_float(po[c]);
    }
    #undef LOADK
    #undef LOADV
    #undef ISSUE_S_BODY
    #undef ISSUE_PV_BODY

    // ---- epilogue: normalize, transpose via smem, coalesced store ----
    __syncthreads();
    float inv = __fdividef(1.f, l);
    float* Os = (float*)(smem + 4096);   // reuse K buf0: [d 64][i 128] stride 132
    #pragma unroll
    for (int c = 0; c < 32; c++)
        Os[(chh*32 + c)*132 + irow] = o_acc[c] * inv;
    __syncthreads();
    #pragma unroll
    for (int it = 0; it < 8; it++) {
        int lin = tid + it*256;
        int d = lin >> 5, i4 = (lin & 31)*4;
        int gi = i0 + i4;
        if (gi < NPIX) {
            float4 v = *(const float4*)&Os[d*132 + i4];
            *(float4*)&out[bo + (size_t)d*NPIX + gi] = v;
        }
    }
    __syncthreads();
    if (wid == 0) TC_DEALLOC(tmem, 512);
#else
    (void)out;
#endif
}

// ---------------------------------------------------------------------------
extern "C" void kernel_launch(void* const* d_in, const int* in_sizes, int n_in,
                              void* d_out, int out_size) {
    const float* x     = (const float*)d_in[0];
    const float* wq    = (const float*)d_in[1];
    const float* bq    = (const float*)d_in[2];
    const float* wk    = (const float*)d_in[3];
    const float* bk    = (const float*)d_in[4];
    const float* wv    = (const float*)d_in[5];
    const float* bv    = (const float*)d_in[6];
    const float* rel_h = (const float*)d_in[7];
    const float* rel_w = (const float*)d_in[8];
    float* out = (float*)d_out;

    cudaFuncSetAttribute(attn_tc_kernel,
                         cudaFuncAttributeMaxDynamicSharedMemorySize, TC_SMEM);
    cudaFuncSetAttribute(qkv_tc_kernel,
                         cudaFuncAttributeMaxDynamicSharedMemorySize, PROJ_SMEM);

    // prep
    dim3 xgrid((NPIX + 31)/32, CH/32, NB);
    split_x_kernel<<<xgrid, dim3(32, 8)>>>(x);
    split_w_kernel<<<(3*CH*CH + 255)/256, 256>>>(wq, wk, wv);
    pos_kernel<<<(HEADS*DH*NPIX + 255)/256, 256>>>(rel_h, rel_w);

    // merged tcgen05 QKV projection (R10/R11 proven config)
    dim3 pgrid(7, 4, NB);
    qkv_tc_kernel<<<pgrid, 256, PROJ_SMEM>>>(bq, bk, bv);

    // pipelined tcgen05 attention (merged commits)
    dim3 tgrid(7, NB*HEADS);
    attn_tc_kernel<<<tgrid, 256, TC_SMEM>>>(out);
}

// round 15
// speedup vs baseline: 1.1724x; 1.0088x over previous
#include <cuda_runtime.h>
#include <cuda_bf16.h>
#include <math.h>
#include <stdint.h>

#define NB    32
#define CH    512
#define WD    28
#define HDIM  28
#define NPIX  784
#define HEADS 8
#define DH    64

#if defined(__CUDA_ARCH__) && (defined(__CUDA_ARCH_FEAT_SM103_ALL) || defined(__CUDA_ARCH_FEAT_SM100_ALL))
#define HAS_TC 1
#else
#define HAS_TC 0
#endif

// ---------------- global scratch (bf16 hi/lo split) ----------------
__device__ __align__(16) __nv_bfloat16 g_xh[NB*NPIX*CH];   // x^T [b][n][c]
__device__ __align__(16) __nv_bfloat16 g_xl[NB*NPIX*CH];
__device__ __align__(16) __nv_bfloat16 g_qh[NB*NPIX*CH];   // q^T [b][n][o]
__device__ __align__(16) __nv_bfloat16 g_ql[NB*NPIX*CH];
__device__ __align__(16) __nv_bfloat16 g_kh[NB*NPIX*CH];
__device__ __align__(16) __nv_bfloat16 g_kl[NB*NPIX*CH];
__device__ __align__(16) __nv_bfloat16 g_voh[NB*CH*NPIX];  // v [b][o][n]
__device__ __align__(16) __nv_bfloat16 g_vol[NB*CH*NPIX];
__device__ __align__(16) __nv_bfloat16 g_ph[HEADS*NPIX*DH]; // pos^T [h][n][d]
__device__ __align__(16) __nv_bfloat16 g_pl[HEADS*NPIX*DH];
__device__ __align__(16) __nv_bfloat16 g_wqh[CH*CH];       // W [o][c]
__device__ __align__(16) __nv_bfloat16 g_wql[CH*CH];
__device__ __align__(16) __nv_bfloat16 g_wkh[CH*CH];
__device__ __align__(16) __nv_bfloat16 g_wkl[CH*CH];
__device__ __align__(16) __nv_bfloat16 g_wvh[CH*CH];
__device__ __align__(16) __nv_bfloat16 g_wvl[CH*CH];

// ---------------- helpers ----------------
__device__ __forceinline__ uint32_t smem_u32(const void* p) {
    uint32_t a;
    asm("{ .reg .u64 t; cvta.to.shared.u64 t, %1; cvt.u32.u64 %0, t; }"
        : "=r"(a) : "l"(p));
    return a;
}
__device__ __forceinline__ void split2(float a, float b, uint32_t& hi, uint32_t& lo) {
    __nv_bfloat16 ah = __float2bfloat16(a);
    __nv_bfloat16 bh = __float2bfloat16(b);
    __nv_bfloat16 al = __float2bfloat16(a - __bfloat162float(ah));
    __nv_bfloat16 bl = __float2bfloat16(b - __bfloat162float(bh));
    __nv_bfloat162 h2; h2.x = ah; h2.y = bh;
    __nv_bfloat162 l2; l2.x = al; l2.y = bl;
    hi = *(uint32_t*)&h2; lo = *(uint32_t*)&l2;
}
__device__ __forceinline__ void split1(float a, __nv_bfloat16& hi, __nv_bfloat16& lo) {
    hi = __float2bfloat16(a);
    lo = __float2bfloat16(a - __bfloat162float(hi));
}

#if HAS_TC
__device__ __forceinline__ uint32_t elect1() {
    uint32_t p;
    asm volatile("{\n\t.reg .pred p;\n\telect.sync _|p, 0xFFFFFFFF;\n\t"
                 "selp.b32 %0, 1, 0, p;\n\t}" : "=r"(p));
    return p;
}
#define TC_ALLOC(sa, n)   asm volatile("tcgen05.alloc.cta_group::1.sync.aligned.shared::cta.b32 [%0], %1;" :: "r"(sa), "r"(n) : "memory")
#define TC_RELINQ()       asm volatile("tcgen05.relinquish_alloc_permit.cta_group::1.sync.aligned;")
#define TC_DEALLOC(t, n)  asm volatile("tcgen05.dealloc.cta_group::1.sync.aligned.b32 %0, %1;" :: "r"(t), "r"(n))
#define TC_COMMIT(mb)     asm volatile("tcgen05.commit.cta_group::1.mbarrier::arrive::one.shared::cluster.b64 [%0];" :: "r"(mb) : "memory")
#define TC_WAIT_LD()      asm volatile("tcgen05.wait::ld.sync.aligned;" ::: "memory")
#define TC_WAIT_ST()      asm volatile("tcgen05.wait::st.sync.aligned;" ::: "memory")
#define TC_FENCE_AFTER()  asm volatile("tcgen05.fence::after_thread_sync;" ::: "memory")
#define TC_FENCE_BEFORE() asm volatile("tcgen05.fence::before_thread_sync;" ::: "memory")
#define FENCE_ASYNC()     asm volatile("fence.proxy.async.shared::cta;" ::: "memory")
#define MBAR_INIT(mb, c)  asm volatile("mbarrier.init.shared.b64 [%0], %1;" :: "r"(mb), "r"(c) : "memory")

#define MBAR_WAIT(mb, par) do {                                              \
    uint32_t _mb = (mb); uint32_t _p = (par); uint32_t _done;                \
    asm volatile("{\n\t.reg .pred p;\n\t"                                    \
        "mbarrier.try_wait.parity.acquire.cta.shared::cta.b64 p, [%1], %2;\n\t" \
        "selp.b32 %0, 1, 0, p;\n\t}"                                         \
        : "=r"(_done) : "r"(_mb), "r"(_p) : "memory");                       \
    if (!_done) {                                                            \
        asm volatile("{\n\t.reg .pred P1;\n\t"                               \
            "WL_%=:\n\t"                                                     \
            "mbarrier.try_wait.parity.acquire.cta.shared::cta.b64 P1, [%0], %1, 0x989680;\n\t" \
            "@P1 bra.uni WD_%=;\n\tbra.uni WL_%=;\n\tWD_%=:\n\t}"            \
            :: "r"(_mb), "r"(_p) : "memory");                                \
    }                                                                        \
} while (0)

#define LDTM_X32(r, addr)                                                    \
    asm volatile("tcgen05.ld.sync.aligned.32x32b.x32.b32 "                   \
        "{%0,%1,%2,%3,%4,%5,%6,%7,%8,%9,%10,%11,%12,%13,%14,%15,"            \
        "%16,%17,%18,%19,%20,%21,%22,%23,%24,%25,%26,%27,%28,%29,%30,%31}, [%32];" \
        : "=r"((r)[0]),"=r"((r)[1]),"=r"((r)[2]),"=r"((r)[3]),               \
          "=r"((r)[4]),"=r"((r)[5]),"=r"((r)[6]),"=r"((r)[7]),               \
          "=r"((r)[8]),"=r"((r)[9]),"=r"((r)[10]),"=r"((r)[11]),             \
          "=r"((r)[12]),"=r"((r)[13]),"=r"((r)[14]),"=r"((r)[15]),           \
          "=r"((r)[16]),"=r"((r)[17]),"=r"((r)[18]),"=r"((r)[19]),           \
          "=r"((r)[20]),"=r"((r)[21]),"=r"((r)[22]),"=r"((r)[23]),           \
          "=r"((r)[24]),"=r"((r)[25]),"=r"((r)[26]),"=r"((r)[27]),           \
          "=r"((r)[28]),"=r"((r)[29]),"=r"((r)[30]),"=r"((r)[31])            \
        : "r"(addr))

#define STTM_X32(addr, r)                                                    \
    asm volatile("tcgen05.st.sync.aligned.32x32b.x32.b32 [%0], "             \
        "{%1,%2,%3,%4,%5,%6,%7,%8,%9,%10,%11,%12,%13,%14,%15,%16,"           \
        "%17,%18,%19,%20,%21,%22,%23,%24,%25,%26,%27,%28,%29,%30,%31,%32};"  \
        :: "r"(addr),                                                        \
           "r"((r)[0]),"r"((r)[1]),"r"((r)[2]),"r"((r)[3]),                  \
           "r"((r)[4]),"r"((r)[5]),"r"((r)[6]),"r"((r)[7]),                  \
           "r"((r)[8]),"r"((r)[9]),"r"((r)[10]),"r"((r)[11]),                \
           "r"((r)[12]),"r"((r)[13]),"r"((r)[14]),"r"((r)[15]),              \
           "r"((r)[16]),"r"((r)[17]),"r"((r)[18]),"r"((r)[19]),              \
           "r"((r)[20]),"r"((r)[21]),"r"((r)[22]),"r"((r)[23]),              \
           "r"((r)[24]),"r"((r)[25]),"r"((r)[26]),"r"((r)[27]),              \
           "r"((r)[28]),"r"((r)[29]),"r"((r)[30]),"r"((r)[31])               \
        : "memory")

__device__ __forceinline__ void mma_f16_ts(uint32_t d, uint32_t a_tmem, uint64_t b,
                                           uint32_t idesc, bool acc) {
    uint32_t en = acc ? 1u : 0u;
    asm volatile("{\n\t.reg .pred p;\n\tsetp.ne.u32 p, %5, 0;\n\t"
        "tcgen05.mma.cta_group::1.kind::f16 [%0], [%1], %2, %3, {%4,%4,%4,%4}, p;\n\t}"
        :: "r"(d), "r"(a_tmem), "l"(b), "r"(idesc), "r"(0u), "r"(en) : "memory");
}
__device__ __forceinline__ uint64_t mkdesc_k(uint32_t addr) {   // SW128, LBO=1, SBO=64
    return ((2ull<<61)|(1ull<<46)|(64ull<<32)|(1ull<<16)) | ((uint64_t)(addr>>4)&0x3FFF);
}
#define IDESC_128 ((1u<<4)|(1u<<7)|(1u<<10)|((128/8)<<17)|((128/16)<<24))
#define IDESC_64  ((1u<<4)|(1u<<7)|(1u<<10)|((64/8)<<17)|((128/16)<<24))

__device__ __forceinline__ uint32_t sw_off(int row, int byte_in_row) {
    uint32_t off = (uint32_t)(row*128 + byte_in_row);
    return off ^ ((off >> 3) & 0x70);
}
#endif  // HAS_TC

// ---------------------------------------------------------------------------
// Prep kernels
// ---------------------------------------------------------------------------
__global__ void pos_kernel(const float* __restrict__ rel_h,
                           const float* __restrict__ rel_w) {
    int idx = blockIdx.x * 256 + threadIdx.x;
    if (idx >= HEADS*DH*NPIX) return;
    int n  = idx % NPIX;
    int hd = idx / NPIX;
    int h = hd >> 6, d = hd & 63;
    float v = rel_h[hd*HDIM + (n % HDIM)] + rel_w[hd*WD + (n / HDIM)];
    __nv_bfloat16 hi, lo;
    split1(v, hi, lo);
    size_t t = ((size_t)h*NPIX + n)*DH + d;
    g_ph[t] = hi; g_pl[t] = lo;
}

// 64x64 tile transpose+split, fully coalesced reads and writes.
__global__ void split_x_kernel(const float* __restrict__ x) {
    __shared__ float t[64][65];
    const int bb = blockIdx.z;
    const int c0 = blockIdx.y * 64;
    const int n0 = blockIdx.x * 64;
    const int tid = threadIdx.x;   // 256

    #pragma unroll
    for (int i = 0; i < 4; i++) {
        int lin = tid + i*256;            // 0..1023 = 64c x 16 float4
        int c = lin >> 4, n4 = (lin & 15) * 4;
        float4 v = {0.f, 0.f, 0.f, 0.f};
        if (n0 + n4 < NPIX)
            v = *(const float4*)&x[((size_t)bb*CH + c0 + c)*NPIX + n0 + n4];
        t[c][n4+0] = v.x; t[c][n4+1] = v.y;
        t[c][n4+2] = v.z; t[c][n4+3] = v.w;
    }
    __syncthreads();
    #pragma unroll
    for (int i = 0; i < 8; i++) {
        int lin = tid + i*256;            // 0..2047 = 64n x 32 (c-pairs)
        int n = lin >> 5, cu = lin & 31;
        if (n0 + n < NPIX) {
            uint32_t hi, lo;
            split2(t[2*cu][n], t[2*cu+1][n], hi, lo);
            size_t d = ((size_t)bb*NPIX + n0 + n)*CH + c0 + 2*cu;
            *(uint32_t*)&g_xh[d] = hi;
            *(uint32_t*)&g_xl[d] = lo;
        }
    }
}

__global__ void split_w_kernel(const float* __restrict__ wq,
                               const float* __restrict__ wk,
                               const float* __restrict__ wv) {
    int idx = blockIdx.x * 256 + threadIdx.x;
    if (idx >= 3*CH*CH) return;
    int m = idx / (CH*CH);
    int e = idx % (CH*CH);
    const float* src = (m == 0) ? wq : (m == 1) ? wk : wv;
    __nv_bfloat16* dh = (m == 0) ? g_wqh : (m == 1) ? g_wkh : g_wvh;
    __nv_bfloat16* dl = (m == 0) ? g_wql : (m == 1) ? g_wkl : g_wvl;
    __nv_bfloat16 hi, lo;
    split1(src[e], hi, lo);
    dh[e] = hi; dl[e] = lo;
}

// ---------------------------------------------------------------------------
// Merged QKV projection — 512 threads (16 warps): warps 0-7 own STTM/epilogue,
// all 16 warps share B-tile loads for 2x memory-level parallelism.
// TMEM: A double-buffer 0-127 | Dq 128-255 | Dk 256-383 | Dv 384-511.
// Commit ck -> mbar[ck&1], parity (ck>>1)&1.
// ---------------------------------------------------------------------------
#define PB_OFF  2048
#define PCHUNK  98304
#define PROJ_SMEM (PB_OFF + 2*PCHUNK)
#define VT_STRIDE 136

__global__ __launch_bounds__(512, 1)
void qkv_tc_kernel(const float* __restrict__ bq,
                   const float* __restrict__ bk,
                   const float* __restrict__ bv) {
#if HAS_TC
    extern __shared__ char smem[];
    const uint32_t sb = smem_u32(smem);
    const int tid = threadIdx.x;
    const int wid = tid >> 5, lid = tid & 31;
    const int chh = (wid >> 2) & 1;           // plane (valid for wid<8)
    const int irow = (wid & 3)*32 + lid;
    const uint32_t woff = (uint32_t)(wid & 3) << 21;
    const int bb = blockIdx.z;
    const int n0 = blockIdx.x * 128;
    const int o0 = blockIdx.y * 128;

    if (wid == 0) { TC_ALLOC(sb + 0, 512); TC_RELINQ(); }
    if (tid == 0) { MBAR_INIT(sb + 8, 1); MBAR_INIT(sb + 16, 1); }
    float* bias_s = (float*)(smem + 64);
    if (tid < 128) {
        bias_s[tid]       = bq[o0 + tid];
        bias_s[128 + tid] = bk[o0 + tid];
        bias_s[256 + tid] = bv[o0 + tid];
    }
    __syncthreads();
    uint32_t tmem;
    asm volatile("ld.shared.b32 %0, [%1];" : "=r"(tmem) : "r"(sb + 0));

    const size_t xb = (size_t)bb*NPIX*CH;
    const int a_row = n0 + irow;
    const bool a_ok = (a_row < NPIX);
    const __nv_bfloat16* Asrc = (chh ? g_xl : g_xh) + xb;

    #define LOADC(ck) do {                                                   \
        int _c0 = (ck)*64, _buf = (ck)&1;                                    \
        if (wid < 8) {                                                       \
            uint32_t ar[32];                                                 \
            const uint32_t* _as = (const uint32_t*)(Asrc + (size_t)a_row*CH + _c0); \
            _Pragma("unroll")                                                \
            for (int c = 0; c < 32; c++) ar[c] = a_ok ? _as[c] : 0u;         \
            STTM_X32(tmem + _buf*64 + chh*32 + woff, ar);                    \
            TC_WAIT_ST();                                                    \
        }                                                                    \
        _Pragma("unroll")                                                    \
        for (int it = 0; it < 12; it++) {                                    \
            int lin = tid + it*512;                                          \
            int reg = lin >> 10;                                             \
            int r   = (lin >> 3) & 127;                                      \
            int u   = lin & 7;                                               \
            const __nv_bfloat16* _src =                                      \
                (reg == 0) ? g_wqh : (reg == 1) ? g_wql :                    \
                (reg == 2) ? g_wkh : (reg == 3) ? g_wkl :                    \
                (reg == 4) ? g_wvh : g_wvl;                                  \
            uint4 v = *(const uint4*)(_src + (size_t)(o0 + r)*CH + _c0 + u*8); \
            *(uint4*)(smem + PB_OFF + _buf*PCHUNK + reg*16384 + sw_off(r, u*16)) = v; \
        }                                                                    \
    } while (0)

    LOADC(0);
    FENCE_ASYNC();
    TC_FENCE_BEFORE();
    __syncthreads();

    for (int ck = 0; ck < 8; ck++) {
        int buf = ck & 1;
        if (wid == 0) {
            TC_FENCE_AFTER();
            if (elect1()) {
                #pragma unroll
                for (int t = 0; t < 3; t++) {
                    uint32_t base = sb + PB_OFF + buf*PCHUNK + t*32768;
                    uint64_t dh = mkdesc_k(base);
                    uint64_t dl = mkdesc_k(base + 16384);
                    uint32_t D = tmem + 128 + t*128;
                    #pragma unroll
                    for (int s = 0; s < 4; s++) {
                        uint32_t aH = tmem + buf*64 + s*8;
                        uint32_t aL = aH + 32;
                        mma_f16_ts(D, aH, dh + s*2, IDESC_128, !(ck == 0 && s == 0));
                        mma_f16_ts(D, aH, dl + s*2, IDESC_128, true);
                        mma_f16_ts(D, aL, dh + s*2, IDESC_128, true);
                    }
                }
                TC_COMMIT(sb + 8 + (uint32_t)(ck & 1)*8);
            }
        }
        if (ck >= 1)
            MBAR_WAIT(sb + 8 + (uint32_t)((ck - 1) & 1)*8, (uint32_t)(((ck - 1) >> 1) & 1));
        if (ck < 7) LOADC(ck + 1);
        FENCE_ASYNC();
        TC_FENCE_BEFORE();
        __syncthreads();
    }
    MBAR_WAIT(sb + 8 + 8, 1u);
    #undef LOADC
    TC_FENCE_AFTER();

    __nv_bfloat16* vsm_h = (__nv_bfloat16*)(smem + PB_OFF);
    __nv_bfloat16* vsm_l = (__nv_bfloat16*)(smem + PB_OFF + 36864);

    #pragma unroll
    for (int t = 0; t < 3; t++) {
        float sv[64];
        if (wid < 8) {
            uint32_t rr[32];
            LDTM_X32(rr, tmem + 128 + t*128 + chh*64);
            TC_WAIT_LD();
            #pragma unroll
            for (int c = 0; c < 32; c++) sv[c] = __uint_as_float(rr[c]);
            LDTM_X32(rr, tmem + 128 + t*128 + chh*64 + 32);
            TC_WAIT_LD();
            #pragma unroll
            for (int c = 0; c < 32; c++) sv[32+c] = __uint_as_float(rr[c]);
            #pragma unroll
            for (int c = 0; c < 64; c++) sv[c] += bias_s[t*128 + chh*64 + c];
        }

        if (t < 2) {
            if (wid < 8 && a_ok) {
                uint32_t hw[32], lw[32];
                #pragma unroll
                for (int c = 0; c < 32; c++) split2(sv[2*c], sv[2*c+1], hw[c], lw[c]);
                __nv_bfloat16* OH = (t == 0) ? g_qh : g_kh;
                __nv_bfloat16* OL = (t == 0) ? g_ql : g_kl;
                size_t d = xb + (size_t)a_row*CH + o0 + chh*64;
                #pragma unroll
                for (int u = 0; u < 4; u++) {
                    *(uint4*)&OH[d + u*16]     = *(uint4*)&hw[u*8];
                    *(uint4*)&OH[d + u*16 + 8] = *(uint4*)&hw[u*8 + 4];
                    *(uint4*)&OL[d + u*16]     = *(uint4*)&lw[u*8];
                    *(uint4*)&OL[d + u*16 + 8] = *(uint4*)&lw[u*8 + 4];
                }
            }
        } else {
            __syncthreads();
            if (wid < 8) {
                #pragma unroll
                for (int c = 0; c < 64; c++) {
                    __nv_bfloat16 hi, lo;
                    split1(sv[c], hi, lo);
                    vsm_h[(chh*64 + c)*VT_STRIDE + irow] = hi;
                    vsm_l[(chh*64 + c)*VT_STRIDE + irow] = lo;
                }
            }
            __syncthreads();
            // coalesced copy-out by all 512 threads: o = tid>>2, quarter = tid&3
            int o = tid >> 2, qd = tid & 3;
            size_t gdst = ((size_t)bb*CH + o0 + o)*NPIX + n0;
            #pragma unroll
            for (int u = 0; u < 4; u++) {
                int n = qd*32 + u*8;
                if (n0 + n < NPIX) {
                    *(uint4*)&g_voh[gdst + n] = *(const uint4*)&vsm_h[o*VT_STRIDE + n];
                    *(uint4*)&g_vol[gdst + n] = *(const uint4*)&vsm_l[o*VT_STRIDE + n];
                }
            }
        }
    }
    __syncthreads();
    if (wid == 0) TC_DEALLOC(tmem, 512);
#else
    (void)bq; (void)bk; (void)bv;
#endif
}

// ---------------------------------------------------------------------------
// Pipelined tensor-core flash attention — merged commit (R12/R14 proven,
// unchanged).
// ---------------------------------------------------------------------------
#define AT_KB(b) (4096 + (b)*65536)
#define AT_VB(b) (4096 + 131072 + (b)*32768)
#define TC_SMEM  (4096 + 131072 + 65536)    /* 200704 B */
#define TMC_QH 0
#define TMC_QL 64
#define TMC_PH 128
#define TMC_PL 192
#define TMC_S  256
#define TMC_O  384

__global__ __launch_bounds__(256, 1)
void attn_tc_kernel(float* __restrict__ out) {
#if HAS_TC
    extern __shared__ char smem[];
    const uint32_t sb = smem_u32(smem);
    const int tid = threadIdx.x;
    const int wid = tid >> 5, lid = tid & 31;
    const int chh = wid >> 2;
    const int irow = (wid & 3)*32 + lid;
    const uint32_t woff = (uint32_t)(wid & 3) << 21;
    const int bh = blockIdx.y;
    const int bb = bh >> 3, h = bh & 7;
    const int i0 = blockIdx.x * 128;

    float* red = (float*)(smem + 64);

    if (wid == 0) { TC_ALLOC(sb + 0, 512); TC_RELINQ(); }
    if (tid == 0) MBAR_INIT(sb + 8, 1);
    __syncthreads();
    uint32_t tmem;
    asm volatile("ld.shared.b32 %0, [%1];" : "=r"(tmem) : "r"(sb + 0));

    const size_t bq = (size_t)bb*NPIX*CH + h*DH;
    const size_t bo = ((size_t)bb*CH + h*DH)*NPIX;

    #define LOADK(_jt, _b) do {                                              \
        int _j0 = (_jt)*128;                                                 \
        _Pragma("unroll")                                                    \
        for (int it = 0; it < 16; it++) {                                    \
            int lin = tid + it*256;                                          \
            int reg = lin >> 10;                                             \
            int j   = (lin >> 3) & 127;                                      \
            int u   = lin & 7;                                               \
            int gj  = _j0 + j;                                               \
            uint4 v = make_uint4(0,0,0,0);                                   \
            if (gj < NPIX) {                                                 \
                size_t rb = bq + (size_t)gj*CH;                              \
                const __nv_bfloat16* src =                                   \
                    (reg == 0) ? &g_kh[rb] : (reg == 1) ? &g_kl[rb] :        \
                    (reg == 2) ? &g_qh[rb] : &g_ql[rb];                      \
                v = *(const uint4*)(src + u*8);                              \
            }                                                                \
            *(uint4*)(smem + AT_KB(_b) + reg*16384 + sw_off(j, u*16)) = v;   \
        }                                                                    \
    } while (0)

    #define LOADV(_jt, _b) do {                                              \
        int _j0 = (_jt)*128;                                                 \
        _Pragma("unroll")                                                    \
        for (int it = 0; it < 8; it++) {                                     \
            int lin = tid + it*256;                                          \
            int reg = lin >> 9;                                              \
            int d   = (lin >> 3) & 63;                                       \
            int u   = lin & 7;                                               \
            int jc  = reg >> 1;                                              \
            int hl  = reg & 1;                                               \
            int gjs = _j0 + jc*64 + u*8;                                     \
            uint4 v = make_uint4(0,0,0,0);                                   \
            const __nv_bfloat16* src = hl ? g_vol : g_voh;                   \
            src += bo + (size_t)d*NPIX;                                      \
            if (gjs + 7 < NPIX) {                                            \
                v = *(const uint4*)(src + gjs);                              \
            } else if (gjs < NPIX) {                                         \
                __nv_bfloat16 tmp[8];                                        \
                _Pragma("unroll")                                            \
                for (int e = 0; e < 8; e++)                                  \
                    tmp[e] = (gjs + e < NPIX) ? src[gjs + e] : __float2bfloat16(0.f); \
                v = *(const uint4*)tmp;                                      \
            }                                                                \
            *(uint4*)(smem + AT_VB(_b) + reg*8192 + sw_off(d, u*16)) = v;    \
        }                                                                    \
    } while (0)

    #define ISSUE_S_BODY(_b) do {                                            \
        _Pragma("unroll")                                                    \
        for (int s = 0; s < 8; s++) {                                        \
            int chunk = s >> 2;                                              \
            uint64_t bh_d = mkdesc_k(sb + AT_KB(_b) + chunk*32768) + (uint64_t)((s&3)*2); \
            uint64_t bl_d = mkdesc_k(sb + AT_KB(_b) + chunk*32768 + 16384) + (uint64_t)((s&3)*2); \
            uint32_t aH = tmem + TMC_QH + s*8;                               \
            uint32_t aL = tmem + TMC_QL + s*8;                               \
            mma_f16_ts(tmem + TMC_S, aH, bh_d, IDESC_128, s != 0);           \
            mma_f16_ts(tmem + TMC_S, aH, bl_d, IDESC_128, true);             \
            mma_f16_ts(tmem + TMC_S, aL, bh_d, IDESC_128, true);             \
        }                                                                    \
    } while (0)

    #define ISSUE_PV_BODY(_b) do {                                           \
        _Pragma("unroll")                                                    \
        for (int s = 0; s < 8; s++) {                                        \
            int chunk = s >> 2;                                              \
            uint64_t bh_d = mkdesc_k(sb + AT_VB(_b) + chunk*16384) + (uint64_t)((s&3)*2); \
            uint64_t bl_d = mkdesc_k(sb + AT_VB(_b) + chunk*16384 + 8192) + (uint64_t)((s&3)*2); \
            uint32_t aH = tmem + TMC_PH + s*8;                               \
            uint32_t aL = tmem + TMC_PL + s*8;                               \
            mma_f16_ts(tmem + TMC_O, aH, bh_d, IDESC_64, s != 0);            \
            mma_f16_ts(tmem + TMC_O, aH, bl_d, IDESC_64, true);              \
            mma_f16_ts(tmem + TMC_O, aL, bh_d, IDESC_64, true);              \
        }                                                                    \
    } while (0)

    // ---- prologue ----
    {
        int gi = i0 + irow;
        uint32_t qr[32];
        const uint32_t* srcq = (chh == 0) ? (const uint32_t*)&g_qh[bq + (size_t)gi*CH]
                                          : (const uint32_t*)&g_ql[bq + (size_t)gi*CH];
        const uint32_t* srcp = (chh == 0) ? (const uint32_t*)&g_ph[((size_t)h*NPIX + gi)*DH]
                                          : (const uint32_t*)&g_pl[((size_t)h*NPIX + gi)*DH];
        uint32_t cb = (chh == 0) ? TMC_QH : TMC_QL;
        #pragma unroll
        for (int c = 0; c < 32; c++) qr[c] = (gi < NPIX) ? srcq[c] : 0u;
        STTM_X32(tmem + cb + woff, qr);
        #pragma unroll
        for (int c = 0; c < 32; c++) qr[c] = (gi < NPIX) ? srcp[c] : 0u;
        STTM_X32(tmem + cb + 32 + woff, qr);
        TC_WAIT_ST();
    }
    LOADK(0, 0);
    LOADK(1, 1);
    LOADV(0, 0);
    FENCE_ASYNC();
    TC_FENCE_BEFORE();
    __syncthreads();
    if (wid == 0) {
        TC_FENCE_AFTER();
        if (elect1()) { ISSUE_S_BODY(0); TC_COMMIT(sb + 8); }   // C0
    }

    float m = -INFINITY, l = 0.f, scale_prev = 0.f;
    float o_acc[32];
    #pragma unroll
    for (int c = 0; c < 32; c++) o_acc[c] = 0.f;

    for (int jt = 0; jt < 7; jt++) {
        const int j0 = jt * 128;
        const int buf = jt & 1, nbuf = buf ^ 1;

        MBAR_WAIT(sb + 8, (uint32_t)(jt & 1));
        TC_FENCE_AFTER();

        if (jt >= 1) {
            uint32_t po[32];
            LDTM_X32(po, tmem + TMC_O + chh*32);
            TC_WAIT_LD();
            #pragma unroll
            for (int c = 0; c < 32; c++)
                o_acc[c] = o_acc[c]*scale_prev + __uint_as_float(po[c]);
        }

        float sv[64];
        {
            uint32_t rr[32];
            LDTM_X32(rr, tmem + TMC_S + chh*64);
            TC_WAIT_LD();
            #pragma unroll
            for (int c = 0; c < 32; c++) sv[c] = __uint_as_float(rr[c]);
            LDTM_X32(rr, tmem + TMC_S + chh*64 + 32);
            TC_WAIT_LD();
            #pragma unroll
            for (int c = 0; c < 32; c++) sv[32+c] = __uint_as_float(rr[c]);
        }
        TC_FENCE_BEFORE();
        __syncthreads();

        float mx = -INFINITY;
        #pragma unroll
        for (int c = 0; c < 64; c++) {
            if (j0 + chh*64 + c >= NPIX) sv[c] = -INFINITY;
            mx = fmaxf(mx, sv[c]);
        }
        red[chh*128 + irow] = mx;
        __syncthreads();
        float mnew = fmaxf(m, fmaxf(red[irow], red[128 + irow]));
        float scale = __expf(m - mnew);
        m = mnew;
        float psum = 0.f;
        #pragma unroll
        for (int c = 0; c < 64; c++) {
            float p = __expf(sv[c] - mnew);
            sv[c] = p;
            psum += p;
        }
        red[256 + chh*128 + irow] = psum;
        __syncthreads();
        l = l*scale + red[256 + irow] + red[256 + 128 + irow];
        scale_prev = scale;

        {
            uint32_t prh[32], prl[32];
            #pragma unroll
            for (int c = 0; c < 32; c++)
                split2(sv[2*c], sv[2*c+1], prh[c], prl[c]);
            STTM_X32(tmem + TMC_PH + chh*32 + woff, prh);
            STTM_X32(tmem + TMC_PL + chh*32 + woff, prl);
            TC_WAIT_ST();
        }
        TC_FENCE_BEFORE();
        __syncthreads();

        if (wid == 0) {
            TC_FENCE_AFTER();
            if (elect1()) {
                ISSUE_PV_BODY(buf);
                if (jt < 6) ISSUE_S_BODY(nbuf);
                TC_COMMIT(sb + 8);
            }
        }

        if (jt + 2 <= 6) LOADK(jt + 2, buf);
        if (jt + 1 <= 6) LOADV(jt + 1, nbuf);
        FENCE_ASYNC();
        TC_FENCE_BEFORE();
    }

    MBAR_WAIT(sb + 8, 1u);
    TC_FENCE_AFTER();
    {
        uint32_t po[32];
        LDTM_X32(po, tmem + TMC_O + chh*32);
        TC_WAIT_LD();
        TC_FENCE_BEFORE();
        #pragma unroll
        for (int c = 0; c < 32; c++)
            o_acc[c] = o_acc[c]*scale_prev + __uint_as_float(po[c]);
    }
    #undef LOADK
    #undef LOADV
    #undef ISSUE_S_BODY
    #undef ISSUE_PV_BODY

    __syncthreads();
    float inv = __fdividef(1.f, l);
    float* Os = (float*)(smem + 4096);
    #pragma unroll
    for (int c = 0; c < 32; c++)
        Os[(chh*32 + c)*132 + irow] = o_acc[c] * inv;
    __syncthreads();
    #pragma unroll
    for (int it = 0; it < 8; it++) {
        int lin = tid + it*256;
        int d = lin >> 5, i4 = (lin & 31)*4;
        int gi = i0 + i4;
        if (gi < NPIX) {
            float4 v = *(const float4*)&Os[d*132 + i4];
            *(float4*)&out[bo + (size_t)d*NPIX + gi] = v;
        }
    }
    __syncthreads();
    if (wid == 0) TC_DEALLOC(tmem, 512);
#else
    (void)out;
#endif
}

// ---------------------------------------------------------------------------
extern "C" void kernel_launch(void* const* d_in, const int* in_sizes, int n_in,
                              void* d_out, int out_size) {
    const float* x     = (const float*)d_in[0];
    const float* wq    = (const float*)d_in[1];
    const float* bq    = (const float*)d_in[2];
    const float* wk    = (const float*)d_in[3];
    const float* bk    = (const float*)d_in[4];
    const float* wv    = (const float*)d_in[5];
    const float* bv    = (const float*)d_in[6];
    const float* rel_h = (const float*)d_in[7];
    const float* rel_w = (const float*)d_in[8];
    float* out = (float*)d_out;

    cudaFuncSetAttribute(attn_tc_kernel,
                         cudaFuncAttributeMaxDynamicSharedMemorySize, TC_SMEM);
    cudaFuncSetAttribute(qkv_tc_kernel,
                         cudaFuncAttributeMaxDynamicSharedMemorySize, PROJ_SMEM);

    // prep
    dim3 xgrid((NPIX + 63)/64, CH/64, NB);
    split_x_kernel<<<xgrid, 256>>>(x);
    split_w_kernel<<<(3*CH*CH + 255)/256, 256>>>(wq, wk, wv);
    pos_kernel<<<(HEADS*DH*NPIX + 255)/256, 256>>>(rel_h, rel_w);

    // merged tcgen05 QKV projection (512 threads for load MLP)
    dim3 pgrid(7, 4, NB);
    qkv_tc_kernel<<<pgrid, 512, PROJ_SMEM>>>(bq, bk, bv);

    // pipelined tcgen05 attention (merged commits)
    dim3 tgrid(7, NB*HEADS);
    attn_tc_kernel<<<tgrid, 256, TC_SMEM>>>(out);
}